// round 9
// baseline (speedup 1.0000x reference)
#include <cuda_runtime.h>
#include <cuda_bf16.h>
#include <math.h>

// Problem constants (fixed shapes per reference)
#define NU_  40000
#define NI_  60000
#define NN_  100000
#define DF_  1024
#define DL_  128
#define DI_  64
#define NE_  1600000

// Scratch buffers (device globals: allocation-guard safe)
__device__ float g_x [(size_t)NN_ * DL_];            // normalized x [N,128]
__device__ __nv_bfloat16 g_xw[(size_t)NN_ * DL_];    // conv output (bf16)
__device__ float g_h [(size_t)NN_ * DL_];            // segment sum
__device__ float g_x2[(size_t)NN_ * DI_];            // layer-1 out [N,64]
// CSR build scratch
__device__ int g_cnt [NN_ + 1];
__device__ int g_offs[NN_ + 1];
__device__ int g_part[128];
__device__ int g_pos [NN_];
__device__ int g_srcs[NE_];

__device__ __forceinline__ float leaky_(float v) { return v > 0.0f ? v : 0.01f * v; }

__device__ __forceinline__ float to_tf32(float x) {
    float r;
    asm("cvt.rna.tf32.f32 %0, %1;" : "=f"(r) : "f"(x));
    return r;
}

__device__ __forceinline__ void mma_tf32(float* d, const unsigned* a, const unsigned* b) {
    asm volatile(
        "mma.sync.aligned.m16n8k8.row.col.f32.tf32.tf32.f32 "
        "{%0,%1,%2,%3}, {%4,%5,%6,%7}, {%8,%9}, {%0,%1,%2,%3};"
        : "+f"(d[0]), "+f"(d[1]), "+f"(d[2]), "+f"(d[3])
        : "r"(a[0]), "r"(a[1]), "r"(a[2]), "r"(a[3]), "r"(b[0]), "r"(b[1]));
}

__device__ __forceinline__ void cp_async16(unsigned dst, const void* src, bool pred) {
    int sz = pred ? 16 : 0;
    asm volatile("cp.async.ca.shared.global [%0], [%1], 16, %2;"
                 :: "r"(dst), "l"(src), "r"(sz));
}
#define CP_COMMIT()      asm volatile("cp.async.commit_group;")
#define CP_WAIT_1()      asm volatile("cp.async.wait_group 1;")

// ---------------------------------------------------------------------------
// MLP GEMM (cp.async 3-stage, NO tf32 cvt — raw fp32 bits into mma = RZ
// truncation; the row-wise L2 normalize cancels the scale-like bias):
//   C[M,128] = normalize_rows(A[M,K] @ B[128,K]^T + bias)
// BM=128, BN=128, BK=32, 256 threads. Dynamic smem 110592 B.
// ---------------------------------------------------------------------------
#define MLP_SSTRIDE 36
#define MLP_STAGE_W (128 * MLP_SSTRIDE)

__global__ __launch_bounds__(256) void mlp_gemm(
    const float* __restrict__ A, const float* __restrict__ B,
    float* __restrict__ C, const float* __restrict__ bias)
{
    constexpr int M = NI_, K = DF_, BK = 32;
    constexpr int MT = 4, NT = 4;           // warps 2x4: WM=64, WN=32
    extern __shared__ float smem[];
    float* sA = smem;                        // [3][128][36]
    float* sB = smem + 3 * MLP_STAGE_W;      // [3][128][36]
    __shared__ float sNorm[128];

    const int t    = threadIdx.x;
    const int wid  = t >> 5;
    const int lane = t & 31;
    const int gid  = lane >> 2;
    const int tidg = lane & 3;
    const int wm   = (wid & 1) * 64;
    const int wn   = (wid >> 1) * 32;
    const int m0   = blockIdx.x * 128;

    const unsigned sA_u = (unsigned)__cvta_generic_to_shared(sA);
    const unsigned sB_u = (unsigned)__cvta_generic_to_shared(sB);

    const int cr = t >> 3;           // copy row base (0..31), +32 per i
    const int cc = t & 7;            // 16B chunk within BK=32 row (8 chunks)

    float acc[MT][NT][4];
#pragma unroll
    for (int i = 0; i < MT; i++)
#pragma unroll
        for (int j = 0; j < NT; j++)
#pragma unroll
            for (int q = 0; q < 4; q++) acc[i][j][q] = 0.0f;

#define MLP_ISSUE(STAGE, IT)                                                  \
    {                                                                         \
        int k0 = (IT) * BK;                                                   \
        _Pragma("unroll")                                                     \
        for (int i = 0; i < 4; i++) {                                         \
            int r = cr + i * 32;                                              \
            unsigned off = (unsigned)(((STAGE) * 128 + r) * MLP_SSTRIDE + cc * 4) * 4u; \
            int arow = m0 + r;                                                \
            cp_async16(sA_u + off, &A[(size_t)arow * K + k0 + cc * 4], arow < M); \
            cp_async16(sB_u + off, &B[(size_t)r * K + k0 + cc * 4], true);    \
        }                                                                     \
    }

    const int nk = K / BK;   // 32
    MLP_ISSUE(0, 0); CP_COMMIT();
    MLP_ISSUE(1, 1); CP_COMMIT();

    int buf = 0;
    for (int it = 0; it < nk; it++) {
        CP_WAIT_1();
        __syncthreads();
        if (it + 2 < nk) {
            int st = (buf + 2 >= 3) ? buf - 1 : buf + 2;
            MLP_ISSUE(st, it + 2);
        }
        CP_COMMIT();   // empty group when no issue keeps wait_group invariant

        const float* pa = sA + buf * MLP_STAGE_W;
        const float* pb = sB + buf * MLP_STAGE_W;
#pragma unroll
        for (int kk = 0; kk < BK; kk += 8) {
            unsigned afrag[MT][4];
#pragma unroll
            for (int mt = 0; mt < MT; mt++) {
                int r = wm + mt * 16 + gid;
                afrag[mt][0] = __float_as_uint(pa[r * MLP_SSTRIDE + kk + tidg]);
                afrag[mt][1] = __float_as_uint(pa[(r + 8) * MLP_SSTRIDE + kk + tidg]);
                afrag[mt][2] = __float_as_uint(pa[r * MLP_SSTRIDE + kk + tidg + 4]);
                afrag[mt][3] = __float_as_uint(pa[(r + 8) * MLP_SSTRIDE + kk + tidg + 4]);
            }
            unsigned bfrag[NT][2];
#pragma unroll
            for (int nt = 0; nt < NT; nt++) {
                int n = wn + nt * 8 + gid;
                bfrag[nt][0] = __float_as_uint(pb[n * MLP_SSTRIDE + kk + tidg]);
                bfrag[nt][1] = __float_as_uint(pb[n * MLP_SSTRIDE + kk + tidg + 4]);
            }
#pragma unroll
            for (int mt = 0; mt < MT; mt++)
#pragma unroll
                for (int nt = 0; nt < NT; nt++)
                    mma_tf32(acc[mt][nt], afrag[mt], bfrag[nt]);
        }
        buf = (buf + 1 >= 3) ? 0 : buf + 1;
    }

    // ---- epilogue: bias, row L2 norm, store ----
    __syncthreads();
    if (t < 128) sNorm[t] = 0.0f;
    __syncthreads();
#pragma unroll
    for (int mt = 0; mt < MT; mt++)
#pragma unroll
        for (int nt = 0; nt < NT; nt++) {
            int col = wn + nt * 8 + 2 * tidg;
#pragma unroll
            for (int half = 0; half < 2; half++) {
                int rl = wm + mt * 16 + gid + half * 8;
                if (m0 + rl >= M) continue;
                float v0 = acc[mt][nt][half * 2 + 0] + bias[col];
                float v1 = acc[mt][nt][half * 2 + 1] + bias[col + 1];
                acc[mt][nt][half * 2 + 0] = v0;
                acc[mt][nt][half * 2 + 1] = v1;
                atomicAdd(&sNorm[rl], v0 * v0 + v1 * v1);
            }
        }
    __syncthreads();
    if (t < 128) sNorm[t] = 1.0f / fmaxf(sqrtf(sNorm[t]), 1e-12f);
    __syncthreads();
#pragma unroll
    for (int mt = 0; mt < MT; mt++)
#pragma unroll
        for (int nt = 0; nt < NT; nt++) {
            int col = wn + nt * 8 + 2 * tidg;
#pragma unroll
            for (int half = 0; half < 2; half++) {
                int rl = wm + mt * 16 + gid + half * 8;
                int row = m0 + rl;
                if (row >= M) continue;
                float inv = sNorm[rl];
                *(float2*)&C[(size_t)row * 128 + col] = make_float2(
                    acc[mt][nt][half * 2 + 0] * inv,
                    acc[mt][nt][half * 2 + 1] * inv);
            }
        }
}

// ---------------------------------------------------------------------------
// Pipelined tf32 tensor-core GEMM (register staged, cvt at smem-store):
//   C[M,BN] = A[M,K] @ B[K,BN]  -> bf16 output (conv paths)
// ---------------------------------------------------------------------------
template <int BN>
__global__ __launch_bounds__(256) void conv_gemm(
    const float* __restrict__ A, const float* __restrict__ B,
    __nv_bfloat16* __restrict__ C, int M, int K)
{
    constexpr int BM = 128, BK = 16;
    constexpr int WARPS_M = (BN == 128) ? 2 : 4;
    constexpr int WM = BM / WARPS_M;
    constexpr int WN = BN / (8 / WARPS_M);
    constexpr int MT = WM / 16;
    constexpr int NT = WN / 8;

    __shared__ __align__(16) float sA[2][BM][BK + 4];
    __shared__ __align__(16) float sB[2][BK][BN + 8];

    const int t    = threadIdx.x;
    const int wid  = t >> 5;
    const int lane = t & 31;
    const int gid  = lane >> 2;
    const int tidg = lane & 3;
    const int wm   = (wid % WARPS_M) * WM;
    const int wn   = (wid / WARPS_M) * WN;
    const int m0   = blockIdx.x * BM;

    constexpr int A_LD = (BM * BK) / (256 * 4);
    constexpr int B_LD = (BN * BK) / (256 * 4);
    float4 aReg[A_LD], bReg[B_LD];

    float acc[MT][NT][4];
#pragma unroll
    for (int i = 0; i < MT; i++)
#pragma unroll
        for (int j = 0; j < NT; j++)
#pragma unroll
            for (int q = 0; q < 4; q++) acc[i][j][q] = 0.0f;

#define CLOAD_A(K0)                                                         \
    _Pragma("unroll")                                                       \
    for (int i = 0; i < A_LD; i++) {                                        \
        int fid = t + i * 256;                                              \
        int r = fid >> 2, k4 = fid & 3;                                     \
        int row = m0 + r;                                                   \
        float4 v = make_float4(0.f, 0.f, 0.f, 0.f);                         \
        if (row < M) v = *(const float4*)&A[(size_t)row * K + (K0) + k4*4]; \
        aReg[i] = v;                                                        \
    }
#define CSTORE_A(BUF)                                                       \
    _Pragma("unroll")                                                       \
    for (int i = 0; i < A_LD; i++) {                                        \
        int fid = t + i * 256;                                              \
        int r = fid >> 2, k4 = fid & 3;                                     \
        float4 v = aReg[i];                                                 \
        v.x = to_tf32(v.x); v.y = to_tf32(v.y);                             \
        v.z = to_tf32(v.z); v.w = to_tf32(v.w);                             \
        *(float4*)&sA[BUF][r][k4 * 4] = v;                                  \
    }
#define CLOAD_B(K0)                                                         \
    _Pragma("unroll")                                                       \
    for (int i = 0; i < B_LD; i++) {                                        \
        int fid = t + i * 256;                                              \
        int kk = fid / (BN / 4), n4 = fid % (BN / 4);                       \
        bReg[i] = *(const float4*)&B[(size_t)((K0) + kk) * BN + n4 * 4];    \
    }
#define CSTORE_B(BUF)                                                       \
    _Pragma("unroll")                                                       \
    for (int i = 0; i < B_LD; i++) {                                        \
        int fid = t + i * 256;                                              \
        int kk = fid / (BN / 4), n4 = fid % (BN / 4);                       \
        float4 v = bReg[i];                                                 \
        v.x = to_tf32(v.x); v.y = to_tf32(v.y);                             \
        v.z = to_tf32(v.z); v.w = to_tf32(v.w);                             \
        *(float4*)&sB[BUF][kk][n4 * 4] = v;                                 \
    }

    const int nk = K / BK;
    CLOAD_A(0); CLOAD_B(0);
    CSTORE_A(0); CSTORE_B(0);
    __syncthreads();

    for (int it = 0; it < nk; it++) {
        const int buf = it & 1;
        if (it + 1 < nk) { CLOAD_A((it + 1) * BK); CLOAD_B((it + 1) * BK); }

#pragma unroll
        for (int kk = 0; kk < BK; kk += 8) {
            unsigned afrag[MT][4];
#pragma unroll
            for (int mt = 0; mt < MT; mt++) {
                int r = wm + mt * 16 + gid;
                afrag[mt][0] = __float_as_uint(sA[buf][r][kk + tidg]);
                afrag[mt][1] = __float_as_uint(sA[buf][r + 8][kk + tidg]);
                afrag[mt][2] = __float_as_uint(sA[buf][r][kk + tidg + 4]);
                afrag[mt][3] = __float_as_uint(sA[buf][r + 8][kk + tidg + 4]);
            }
            unsigned bfrag[NT][2];
#pragma unroll
            for (int nt = 0; nt < NT; nt++) {
                int n = wn + nt * 8 + gid;
                bfrag[nt][0] = __float_as_uint(sB[buf][kk + tidg][n]);
                bfrag[nt][1] = __float_as_uint(sB[buf][kk + tidg + 4][n]);
            }
#pragma unroll
            for (int mt = 0; mt < MT; mt++)
#pragma unroll
                for (int nt = 0; nt < NT; nt++)
                    mma_tf32(acc[mt][nt], afrag[mt], bfrag[nt]);
        }
        if (it + 1 < nk) {
            CSTORE_A(buf ^ 1); CSTORE_B(buf ^ 1);
            __syncthreads();
        }
    }

#pragma unroll
    for (int mt = 0; mt < MT; mt++)
#pragma unroll
        for (int nt = 0; nt < NT; nt++) {
            int col = wn + nt * 8 + 2 * tidg;
#pragma unroll
            for (int half = 0; half < 2; half++) {
                int row = m0 + wm + mt * 16 + gid + half * 8;
                if (row >= M) continue;
                *(__nv_bfloat162*)&C[(size_t)row * BN + col] =
                    __floats2bfloat162_rn(acc[mt][nt][half * 2 + 0],
                                          acc[mt][nt][half * 2 + 1]);
            }
        }
#undef CLOAD_A
#undef CSTORE_A
#undef CLOAD_B
#undef CSTORE_B
}

// ---------------------------------------------------------------------------
// Dual GEMM (fused lin + g per layer), BN=64, BK=8 double-buffered:
//   C = leaky( (leaky(A2) @ W2^T) + b2 + leaky(A1 @ W1^T + b1) + id )
// ---------------------------------------------------------------------------
__global__ __launch_bounds__(256) void dual_gemm(
    const float* __restrict__ A1, const float* __restrict__ A2,
    const float* __restrict__ W1, const float* __restrict__ W2,
    const float* __restrict__ b1, const float* __restrict__ b2,
    const float* __restrict__ id_emb, float* __restrict__ C,
    int M, int K)
{
    constexpr int BM = 128, BN = 64, BK = 8;
    constexpr int WM = 32, WN = 32, MT = 2, NT = 4;

    __shared__ __align__(16) float sA1[2][BM][BK + 4];
    __shared__ __align__(16) float sA2[2][BM][BK + 4];
    __shared__ __align__(16) float sB[2][2 * BN][BK + 4];

    const int t    = threadIdx.x;
    const int wid  = t >> 5;
    const int lane = t & 31;
    const int gid  = lane >> 2;
    const int tidg = lane & 3;
    const int wm   = (wid & 3) * WM;
    const int wn   = (wid >> 2) * WN;
    const int m0   = blockIdx.x * BM;

    float4 a1Reg, a2Reg, bReg;
    const int lr  = t >> 1;
    const int lk4 = t & 1;

    float acc1[MT][NT][4], acc2[MT][NT][4];
#pragma unroll
    for (int i = 0; i < MT; i++)
#pragma unroll
        for (int j = 0; j < NT; j++)
#pragma unroll
            for (int q = 0; q < 4; q++) { acc1[i][j][q] = 0.f; acc2[i][j][q] = 0.f; }

#define DLOAD(K0)                                                             \
    {                                                                         \
        int row = m0 + lr;                                                    \
        a1Reg = make_float4(0.f, 0.f, 0.f, 0.f);                              \
        a2Reg = make_float4(0.f, 0.f, 0.f, 0.f);                              \
        if (row < M) {                                                        \
            a1Reg = *(const float4*)&A1[(size_t)row * K + (K0) + lk4 * 4];    \
            a2Reg = *(const float4*)&A2[(size_t)row * K + (K0) + lk4 * 4];    \
        }                                                                     \
        const float* Wp = (lr < BN) ? &W1[(size_t)lr * K]                     \
                                    : &W2[(size_t)(lr - BN) * K];             \
        bReg = *(const float4*)&Wp[(K0) + lk4 * 4];                           \
    }
#define DSTORE(BUF)                                                           \
    {                                                                         \
        float4 v = a1Reg;                                                     \
        v.x = to_tf32(v.x); v.y = to_tf32(v.y);                               \
        v.z = to_tf32(v.z); v.w = to_tf32(v.w);                               \
        *(float4*)&sA1[BUF][lr][lk4 * 4] = v;                                 \
        v = a2Reg;                                                            \
        v.x = to_tf32(leaky_(v.x)); v.y = to_tf32(leaky_(v.y));               \
        v.z = to_tf32(leaky_(v.z)); v.w = to_tf32(leaky_(v.w));               \
        *(float4*)&sA2[BUF][lr][lk4 * 4] = v;                                 \
        v = bReg;                                                             \
        v.x = to_tf32(v.x); v.y = to_tf32(v.y);                               \
        v.z = to_tf32(v.z); v.w = to_tf32(v.w);                               \
        *(float4*)&sB[BUF][lr][lk4 * 4] = v;                                  \
    }

    const int nk = K / BK;
    DLOAD(0); DSTORE(0);
    __syncthreads();

    for (int it = 0; it < nk; it++) {
        const int buf = it & 1;
        if (it + 1 < nk) DLOAD((it + 1) * BK);

        unsigned af1[MT][4], af2[MT][4];
#pragma unroll
        for (int mt = 0; mt < MT; mt++) {
            int r = wm + mt * 16 + gid;
            af1[mt][0] = __float_as_uint(sA1[buf][r][tidg]);
            af1[mt][1] = __float_as_uint(sA1[buf][r + 8][tidg]);
            af1[mt][2] = __float_as_uint(sA1[buf][r][tidg + 4]);
            af1[mt][3] = __float_as_uint(sA1[buf][r + 8][tidg + 4]);
            af2[mt][0] = __float_as_uint(sA2[buf][r][tidg]);
            af2[mt][1] = __float_as_uint(sA2[buf][r + 8][tidg]);
            af2[mt][2] = __float_as_uint(sA2[buf][r][tidg + 4]);
            af2[mt][3] = __float_as_uint(sA2[buf][r + 8][tidg + 4]);
        }
        unsigned bf1[NT][2], bf2[NT][2];
#pragma unroll
        for (int nt = 0; nt < NT; nt++) {
            int n = wn + nt * 8 + gid;
            bf1[nt][0] = __float_as_uint(sB[buf][n][tidg]);
            bf1[nt][1] = __float_as_uint(sB[buf][n][tidg + 4]);
            bf2[nt][0] = __float_as_uint(sB[buf][n + BN][tidg]);
            bf2[nt][1] = __float_as_uint(sB[buf][n + BN][tidg + 4]);
        }
#pragma unroll
        for (int mt = 0; mt < MT; mt++)
#pragma unroll
            for (int nt = 0; nt < NT; nt++) {
                mma_tf32(acc1[mt][nt], af1[mt], bf1[nt]);
                mma_tf32(acc2[mt][nt], af2[mt], bf2[nt]);
            }

        if (it + 1 < nk) {
            DSTORE(buf ^ 1);
            __syncthreads();
        }
    }

#pragma unroll
    for (int mt = 0; mt < MT; mt++)
#pragma unroll
        for (int nt = 0; nt < NT; nt++) {
            int col = wn + nt * 8 + 2 * tidg;
#pragma unroll
            for (int half = 0; half < 2; half++) {
                int row = m0 + wm + mt * 16 + gid + half * 8;
                if (row >= M) continue;
                float xh0 = leaky_(acc1[mt][nt][half * 2 + 0] + b1[col])
                          + id_emb[(size_t)row * BN + col];
                float xh1 = leaky_(acc1[mt][nt][half * 2 + 1] + b1[col + 1])
                          + id_emb[(size_t)row * BN + col + 1];
                float v0 = leaky_(acc2[mt][nt][half * 2 + 0] + b2[col] + xh0);
                float v1 = leaky_(acc2[mt][nt][half * 2 + 1] + b2[col + 1] + xh1);
                *(float2*)&C[(size_t)row * BN + col] = make_float2(v0, v1);
            }
        }
#undef DLOAD
#undef DSTORE
}

// ---------------------------------------------------------------------------
// Fused copy + row-wise L2 normalize for preference rows (D=128, warp/row)
// ---------------------------------------------------------------------------
__global__ void pref_norm_kernel(const float* __restrict__ src,
                                 float* __restrict__ dst, int nrows)
{
    int warp = (blockIdx.x * blockDim.x + threadIdx.x) >> 5;
    int lane = threadIdx.x & 31;
    if (warp >= nrows) return;
    float4 v = *(const float4*)&src[(size_t)warp * 128 + lane * 4];
    float ss = v.x * v.x + v.y * v.y + v.z * v.z + v.w * v.w;
#pragma unroll
    for (int o = 16; o; o >>= 1) ss += __shfl_xor_sync(0xffffffffu, ss, o);
    float inv = 1.0f / fmaxf(sqrtf(ss), 1e-12f);
    v.x *= inv; v.y *= inv; v.z *= inv; v.w *= inv;
    *(float4*)&dst[(size_t)warp * 128 + lane * 4] = v;
}

// ---------------------------------------------------------------------------
// CSR build: histogram of dst, 3-phase exclusive scan, src reorder by dst
// ---------------------------------------------------------------------------
__global__ void hist_kernel(const int* __restrict__ ei, int* __restrict__ cnt)
{
    int e = blockIdx.x * blockDim.x + threadIdx.x;
    if (e < NE_) atomicAdd(&cnt[__ldg(&ei[NE_ + e])], 1);
}

__global__ void scan1_kernel(const int* __restrict__ in, int* __restrict__ out,
                             int* __restrict__ part, int n)
{
    __shared__ int s[1024];
    int i = blockIdx.x * 1024 + threadIdx.x;
    int v = (i < n) ? in[i] : 0;
    s[threadIdx.x] = v;
    __syncthreads();
#pragma unroll
    for (int o = 1; o < 1024; o <<= 1) {
        int y = (threadIdx.x >= o) ? s[threadIdx.x - o] : 0;
        __syncthreads();
        s[threadIdx.x] += y;
        __syncthreads();
    }
    if (i < n) out[i] = s[threadIdx.x] - v;
    if (threadIdx.x == 1023) part[blockIdx.x] = s[1023];
}

__global__ void scan2_kernel(int* __restrict__ part, int nb)
{
    __shared__ int s[128];
    int v = (threadIdx.x < nb) ? part[threadIdx.x] : 0;
    s[threadIdx.x] = v;
    __syncthreads();
#pragma unroll
    for (int o = 1; o < 128; o <<= 1) {
        int y = (threadIdx.x >= o) ? s[threadIdx.x - o] : 0;
        __syncthreads();
        s[threadIdx.x] += y;
        __syncthreads();
    }
    if (threadIdx.x < nb) part[threadIdx.x] = s[threadIdx.x] - v;  // exclusive
}

__global__ void scan3_kernel(int* __restrict__ out, const int* __restrict__ part, int n)
{
    int i = blockIdx.x * 1024 + threadIdx.x;
    if (i < n) out[i] += part[blockIdx.x];
}

__global__ void reorder_kernel(const int* __restrict__ ei, int* __restrict__ pos,
                               int* __restrict__ srcs)
{
    int e = blockIdx.x * blockDim.x + threadIdx.x;
    if (e >= NE_) return;
    int d = __ldg(&ei[NE_ + e]);
    int idx = atomicAdd(&pos[d], 1);
    srcs[idx] = __ldg(&ei[e]);
}

// ---------------------------------------------------------------------------
// Atomic-free segmented scatter over bf16 xw (16B lanes):
//   h[d] = sum_{e: dst=d} float(xw[srcs[e]])
// ---------------------------------------------------------------------------
template <int D>
__global__ void seg_scatter(const __nv_bfloat16* __restrict__ xw,
                            const int* __restrict__ offs,
                            const int* __restrict__ srcs,
                            float* __restrict__ h)
{
    constexpr int G = D / 8;       // 16B (8 bf16) chunks per row
    int gt   = blockIdx.x * blockDim.x + threadIdx.x;
    int node = gt / G;
    int q    = threadIdx.x % G;
    if (node >= NN_) return;

    int s   = __ldg(&offs[node]);
    int end = __ldg(&offs[node + 1]);

    float a[8] = {0,0,0,0,0,0,0,0};
    float b[8] = {0,0,0,0,0,0,0,0};

#define ACC8(dst, u)                                                        \
    {                                                                       \
        float2 f;                                                           \
        f = __bfloat1622float2(*(const __nv_bfloat162*)&(u).x);             \
        dst[0] += f.x; dst[1] += f.y;                                       \
        f = __bfloat1622float2(*(const __nv_bfloat162*)&(u).y);             \
        dst[2] += f.x; dst[3] += f.y;                                       \
        f = __bfloat1622float2(*(const __nv_bfloat162*)&(u).z);             \
        dst[4] += f.x; dst[5] += f.y;                                       \
        f = __bfloat1622float2(*(const __nv_bfloat162*)&(u).w);             \
        dst[6] += f.x; dst[7] += f.y;                                       \
    }

    int i = s;
    for (; i + 3 < end; i += 4) {
        int s0 = __ldg(&srcs[i + 0]);
        int s1 = __ldg(&srcs[i + 1]);
        int s2 = __ldg(&srcs[i + 2]);
        int s3 = __ldg(&srcs[i + 3]);
        uint4 u0 = *(const uint4*)&xw[(size_t)s0 * D + q * 8];
        uint4 u1 = *(const uint4*)&xw[(size_t)s1 * D + q * 8];
        uint4 u2 = *(const uint4*)&xw[(size_t)s2 * D + q * 8];
        uint4 u3 = *(const uint4*)&xw[(size_t)s3 * D + q * 8];
        ACC8(a, u0); ACC8(b, u1); ACC8(a, u2); ACC8(b, u3);
    }
    for (; i < end; i++) {
        int s0 = __ldg(&srcs[i]);
        uint4 u0 = *(const uint4*)&xw[(size_t)s0 * D + q * 8];
        ACC8(a, u0);
    }
#undef ACC8

    float4 r0 = make_float4(a[0] + b[0], a[1] + b[1], a[2] + b[2], a[3] + b[3]);
    float4 r1 = make_float4(a[4] + b[4], a[5] + b[5], a[6] + b[6], a[7] + b[7]);
    *(float4*)&h[(size_t)node * D + q * 8]     = r0;
    *(float4*)&h[(size_t)node * D + q * 8 + 4] = r1;
}

// ---------------------------------------------------------------------------
extern "C" void kernel_launch(void* const* d_in, const int* in_sizes, int n_in,
                              void* d_out, int out_size)
{
    const float* features = (const float*)d_in[0];
    const float* id_emb   = (const float*)d_in[1];
    const float* pref     = (const float*)d_in[2];
    const float* mlp_w    = (const float*)d_in[3];
    const float* mlp_b    = (const float*)d_in[4];
    const float* conv1_w  = (const float*)d_in[5];
    const float* lin1_w   = (const float*)d_in[6];
    const float* lin1_b   = (const float*)d_in[7];
    const float* g1_w     = (const float*)d_in[8];
    const float* g1_b     = (const float*)d_in[9];
    const float* conv2_w  = (const float*)d_in[10];
    const float* lin2_w   = (const float*)d_in[11];
    const float* lin2_b   = (const float*)d_in[12];
    const float* g2_w     = (const float*)d_in[13];
    const float* g2_b     = (const float*)d_in[14];
    const int*   ei       = (const int*)d_in[15];
    float* out = (float*)d_out;

    float *px, *ph, *px2;
    __nv_bfloat16* pxw;
    int *pcnt, *poffs, *ppart, *ppos, *psrcs;
    cudaGetSymbolAddress((void**)&px,    g_x);
    cudaGetSymbolAddress((void**)&pxw,   g_xw);
    cudaGetSymbolAddress((void**)&ph,    g_h);
    cudaGetSymbolAddress((void**)&px2,   g_x2);
    cudaGetSymbolAddress((void**)&pcnt,  g_cnt);
    cudaGetSymbolAddress((void**)&poffs, g_offs);
    cudaGetSymbolAddress((void**)&ppart, g_part);
    cudaGetSymbolAddress((void**)&ppos,  g_pos);
    cudaGetSymbolAddress((void**)&psrcs, g_srcs);

    const int GB_N  = (NN_ + 127) / 128;
    const int NSCAN = NN_ + 1;
    const int NBLK  = (NSCAN + 1023) / 1024;
    const int MLP_SMEM = 2 * 3 * 128 * MLP_SSTRIDE * 4;   // 110592 B

    static cudaStream_t s_csr = nullptr;
    static cudaEvent_t ev_fork = nullptr, ev_join = nullptr;
    if (!s_csr) {
        cudaStreamCreateWithFlags(&s_csr, cudaStreamNonBlocking);
        cudaEventCreateWithFlags(&ev_fork, cudaEventDisableTiming);
        cudaEventCreateWithFlags(&ev_join, cudaEventDisableTiming);
        cudaFuncSetAttribute(mlp_gemm,
                             cudaFuncAttributeMaxDynamicSharedMemorySize, MLP_SMEM);
    }

    // ---- fork: CSR build + pref_norm on side stream ----
    cudaEventRecord(ev_fork, 0);
    cudaStreamWaitEvent(s_csr, ev_fork, 0);
    cudaMemsetAsync(pcnt, 0, NSCAN * sizeof(int), s_csr);
    hist_kernel<<<(NE_ + 255) / 256, 256, 0, s_csr>>>(ei, pcnt);
    scan1_kernel<<<NBLK, 1024, 0, s_csr>>>(pcnt, poffs, ppart, NSCAN);
    scan2_kernel<<<1, 128, 0, s_csr>>>(ppart, NBLK);
    scan3_kernel<<<NBLK, 1024, 0, s_csr>>>(poffs, ppart, NSCAN);
    cudaMemcpyAsync(ppos, poffs, NN_ * sizeof(int), cudaMemcpyDeviceToDevice, s_csr);
    reorder_kernel<<<(NE_ + 255) / 256, 256, 0, s_csr>>>(ei, ppos, psrcs);
    pref_norm_kernel<<<(NU_ * 32 + 255) / 256, 256, 0, s_csr>>>(pref, px, NU_);
    cudaEventRecord(ev_join, s_csr);

    // ---- main stream ----
    mlp_gemm<<<(NI_ + 127) / 128, 256, MLP_SMEM>>>(
        features, mlp_w, px + (size_t)NU_ * DL_, mlp_b);
    cudaStreamWaitEvent(0, ev_join, 0);   // join: pref rows + CSR ready

    // ===== layer 1 =====
    conv_gemm<128><<<GB_N, 256>>>(px, conv1_w, pxw, NN_, DL_);
    seg_scatter<128><<<(NN_ * 16 + 255) / 256, 256>>>(pxw, poffs, psrcs, ph);
    dual_gemm<<<GB_N, 256>>>(px, ph, lin1_w, g1_w, lin1_b, g1_b, id_emb, px2, NN_, DL_);

    // ===== layer 2 =====
    conv_gemm<64><<<GB_N, 256>>>(px2, conv2_w, pxw, NN_, DI_);
    seg_scatter<64><<<(NN_ * 8 + 255) / 256, 256>>>(pxw, poffs, psrcs, ph);
    dual_gemm<<<GB_N, 256>>>(px2, ph, lin2_w, g2_w, lin2_b, g2_b, id_emb, out, NN_, DI_);
}

// round 11
// speedup vs baseline: 1.2845x; 1.2845x over previous
#include <cuda_runtime.h>
#include <cuda_bf16.h>
#include <math.h>

// Problem constants (fixed shapes per reference)
#define NU_  40000
#define NI_  60000
#define NN_  100000
#define DF_  1024
#define DL_  128
#define DI_  64
#define NE_  1600000

// Scratch buffers (device globals: allocation-guard safe)
__device__ float g_x [(size_t)NN_ * DL_];            // normalized x [N,128]
__device__ __align__(16) __nv_bfloat16 g_xw[(size_t)NN_ * DL_];  // conv out (bf16)
__device__ float g_h [(size_t)NN_ * DL_];            // segment sum
__device__ float g_x2[(size_t)NN_ * DI_];            // layer-1 out [N,64]
// bf16 transposed weight copies (built on side stream)
__device__ __align__(16) __nv_bfloat16 g_wc1[DL_ * DL_];  // conv1_w^T [n][k]
__device__ __align__(16) __nv_bfloat16 g_wc2[DI_ * DI_];  // conv2_w^T [n][k]
// CSR build scratch
__device__ int g_cnt [NN_ + 1];
__device__ int g_offs[NN_ + 1];
__device__ int g_part[128];
__device__ int g_pos [NN_];
__device__ int g_srcs[NE_];

__device__ __forceinline__ float leaky_(float v) { return v > 0.0f ? v : 0.01f * v; }

__device__ __forceinline__ unsigned f2bf2(float lo, float hi) {
    __nv_bfloat162 h = __floats2bfloat162_rn(lo, hi);
    return *reinterpret_cast<unsigned*>(&h);
}

// bf16 m16n8k16 mma, fp32 accumulate
__device__ __forceinline__ void mma_bf16(float* d, const unsigned* a, const unsigned* b) {
    asm volatile(
        "mma.sync.aligned.m16n8k16.row.col.f32.bf16.bf16.f32 "
        "{%0,%1,%2,%3}, {%4,%5,%6,%7}, {%8,%9}, {%0,%1,%2,%3};"
        : "+f"(d[0]), "+f"(d[1]), "+f"(d[2]), "+f"(d[3])
        : "r"(a[0]), "r"(a[1]), "r"(a[2]), "r"(a[3]), "r"(b[0]), "r"(b[1]));
}

// ---------------------------------------------------------------------------
// bf16 tensor-core GEMM: C[M,BN] = A[M,K] @ B[BN,K]^T   (B is [n][k])
//   BBF16: B is bf16 in gmem (direct smem copy); else fp32 (cvt at store)
//   NORM: row-wise L2-normalize output (bias added first; fp32 out)
//   OUTBF16: bf16 output (conv paths)
// BM=128, BK=16 double-buffered (register staged), 256 threads.
// smem tiles are bf16 packed 2-per-word, row stride SW=12 words
// (12r+t mod 32 distinct for all lanes -> conflict-free fragment LDS).
// ---------------------------------------------------------------------------
template <int BN, bool NORM, bool OUTBF16, bool BBF16>
__global__ __launch_bounds__(256) void mma_gemm(
    const float* __restrict__ A, const void* __restrict__ Bv,
    void* __restrict__ Cv, int M, int K, const float* __restrict__ bias)
{
    constexpr int BM = 128, BK = 16, SW = 12;   // SW words = 24 bf16 per row
    constexpr int WARPS_M = (BN == 128) ? 2 : 4;
    constexpr int WM = BM / WARPS_M;            // 64 or 32
    constexpr int MT = WM / 16;                 // 4 or 2
    constexpr int NT = 4;                       // WN=32

    __shared__ unsigned sA[2][BM * SW];
    __shared__ unsigned sB[2][BN * SW];
    __shared__ float sNorm[NORM ? BM : 1];

    const int t    = threadIdx.x;
    const int wid  = t >> 5;
    const int lane = t & 31;
    const int gid  = lane >> 2;
    const int tidg = lane & 3;
    const int wm   = (wid % WARPS_M) * WM;
    const int wn   = (wid / WARPS_M) * 32;
    const int m0   = blockIdx.x * BM;

    float4 aReg[2];
    float4 bRegF[2];
    uint4  bRegV4;
    uint2  bRegV2;

    float acc[MT][NT][4];
#pragma unroll
    for (int i = 0; i < MT; i++)
#pragma unroll
        for (int j = 0; j < NT; j++)
#pragma unroll
            for (int q = 0; q < 4; q++) acc[i][j][q] = 0.0f;

#define LOAD_A(K0)                                                            \
    _Pragma("unroll")                                                         \
    for (int i = 0; i < 2; i++) {                                             \
        int fid = t + i * 256;                                                \
        int r = fid >> 2, k4 = fid & 3;                                       \
        int row = m0 + r;                                                     \
        float4 v = make_float4(0.f, 0.f, 0.f, 0.f);                           \
        if (row < M) v = *(const float4*)&A[(size_t)row * K + (K0) + k4 * 4]; \
        aReg[i] = v;                                                          \
    }

#define STORE_A(BUF)                                                          \
    _Pragma("unroll")                                                         \
    for (int i = 0; i < 2; i++) {                                             \
        int fid = t + i * 256;                                                \
        int r = fid >> 2, k4 = fid & 3;                                       \
        float4 v = aReg[i];                                                   \
        uint2 u = make_uint2(f2bf2(v.x, v.y), f2bf2(v.z, v.w));               \
        *(uint2*)&sA[BUF][r * SW + k4 * 2] = u;                               \
    }

#define LOAD_B(K0)                                                            \
    if (BBF16) {                                                              \
        const __nv_bfloat16* Bb = (const __nv_bfloat16*)Bv;                   \
        if (BN == 128) {                                                      \
            int n = t >> 1, h = t & 1;                                        \
            bRegV4 = *(const uint4*)&Bb[(size_t)n * K + (K0) + h * 8];        \
        } else {                                                              \
            int n = t >> 2, q = t & 3;                                        \
            bRegV2 = *(const uint2*)&Bb[(size_t)n * K + (K0) + q * 4];        \
        }                                                                     \
    } else {                                                                  \
        const float* Bf = (const float*)Bv;                                   \
        if (BN == 128) {                                                      \
            _Pragma("unroll")                                                 \
            for (int i = 0; i < 2; i++) {                                     \
                int fid = t + i * 256;                                        \
                int n = fid >> 2, k4 = fid & 3;                               \
                bRegF[i] = *(const float4*)&Bf[(size_t)n * K + (K0) + k4*4];  \
            }                                                                 \
        } else {                                                              \
            int n = t >> 2, k4 = t & 3;                                       \
            bRegF[0] = *(const float4*)&Bf[(size_t)n * K + (K0) + k4 * 4];    \
        }                                                                     \
    }

#define STORE_B(BUF)                                                          \
    if (BBF16) {                                                              \
        if (BN == 128) {                                                      \
            int n = t >> 1, h = t & 1;                                        \
            *(uint4*)&sB[BUF][n * SW + h * 4] = bRegV4;                       \
        } else {                                                              \
            int n = t >> 2, q = t & 3;                                        \
            *(uint2*)&sB[BUF][n * SW + q * 2] = bRegV2;                       \
        }                                                                     \
    } else {                                                                  \
        if (BN == 128) {                                                      \
            _Pragma("unroll")                                                 \
            for (int i = 0; i < 2; i++) {                                     \
                int fid = t + i * 256;                                        \
                int n = fid >> 2, k4 = fid & 3;                               \
                float4 v = bRegF[i];                                          \
                uint2 u = make_uint2(f2bf2(v.x, v.y), f2bf2(v.z, v.w));       \
                *(uint2*)&sB[BUF][n * SW + k4 * 2] = u;                       \
            }                                                                 \
        } else {                                                              \
            int n = t >> 2, k4 = t & 3;                                       \
            float4 v = bRegF[0];                                              \
            uint2 u = make_uint2(f2bf2(v.x, v.y), f2bf2(v.z, v.w));           \
            *(uint2*)&sB[BUF][n * SW + k4 * 2] = u;                           \
        }                                                                     \
    }

    const int nk = K / BK;
    LOAD_A(0); LOAD_B(0);
    STORE_A(0); STORE_B(0);
    __syncthreads();

    for (int it = 0; it < nk; it++) {
        const int buf = it & 1;
        if (it + 1 < nk) { LOAD_A((it + 1) * BK); LOAD_B((it + 1) * BK); }

        // one k16 step per tile
        unsigned af[MT][4];
#pragma unroll
        for (int mt = 0; mt < MT; mt++) {
            int base = (wm + mt * 16 + gid) * SW;
            af[mt][0] = sA[buf][base + tidg];
            af[mt][1] = sA[buf][base + 8 * SW + tidg];
            af[mt][2] = sA[buf][base + tidg + 4];
            af[mt][3] = sA[buf][base + 8 * SW + tidg + 4];
        }
        unsigned bf[NT][2];
#pragma unroll
        for (int nt = 0; nt < NT; nt++) {
            int nb = (wn + nt * 8 + gid) * SW;
            bf[nt][0] = sB[buf][nb + tidg];
            bf[nt][1] = sB[buf][nb + tidg + 4];
        }
#pragma unroll
        for (int mt = 0; mt < MT; mt++)
#pragma unroll
            for (int nt = 0; nt < NT; nt++)
                mma_bf16(acc[mt][nt], af[mt], bf[nt]);

        if (it + 1 < nk) {
            STORE_A(buf ^ 1); STORE_B(buf ^ 1);
            __syncthreads();
        }
    }

    if (NORM) {
        float* C = (float*)Cv;
        if (t < BM) sNorm[t] = 0.0f;
        __syncthreads();
#pragma unroll
        for (int mt = 0; mt < MT; mt++)
#pragma unroll
            for (int nt = 0; nt < NT; nt++) {
                int col = wn + nt * 8 + 2 * tidg;
#pragma unroll
                for (int half = 0; half < 2; half++) {
                    int rl = wm + mt * 16 + gid + half * 8;
                    if (m0 + rl >= M) continue;
                    float v0 = acc[mt][nt][half * 2 + 0] + bias[col];
                    float v1 = acc[mt][nt][half * 2 + 1] + bias[col + 1];
                    acc[mt][nt][half * 2 + 0] = v0;
                    acc[mt][nt][half * 2 + 1] = v1;
                    atomicAdd(&sNorm[rl], v0 * v0 + v1 * v1);
                }
            }
        __syncthreads();
        if (t < BM) sNorm[t] = 1.0f / fmaxf(sqrtf(sNorm[t]), 1e-12f);
        __syncthreads();
#pragma unroll
        for (int mt = 0; mt < MT; mt++)
#pragma unroll
            for (int nt = 0; nt < NT; nt++) {
                int col = wn + nt * 8 + 2 * tidg;
#pragma unroll
                for (int half = 0; half < 2; half++) {
                    int rl = wm + mt * 16 + gid + half * 8;
                    int row = m0 + rl;
                    if (row >= M) continue;
                    float inv = sNorm[rl];
                    *(float2*)&C[(size_t)row * BN + col] = make_float2(
                        acc[mt][nt][half * 2 + 0] * inv,
                        acc[mt][nt][half * 2 + 1] * inv);
                }
            }
    } else {
#pragma unroll
        for (int mt = 0; mt < MT; mt++)
#pragma unroll
            for (int nt = 0; nt < NT; nt++) {
                int col = wn + nt * 8 + 2 * tidg;
#pragma unroll
                for (int half = 0; half < 2; half++) {
                    int row = m0 + wm + mt * 16 + gid + half * 8;
                    if (row >= M) continue;
                    float v0 = acc[mt][nt][half * 2 + 0];
                    float v1 = acc[mt][nt][half * 2 + 1];
                    if (OUTBF16) {
                        __nv_bfloat16* C = (__nv_bfloat16*)Cv;
                        *(__nv_bfloat162*)&C[(size_t)row * BN + col] =
                            __floats2bfloat162_rn(v0, v1);
                    } else {
                        float* C = (float*)Cv;
                        *(float2*)&C[(size_t)row * BN + col] = make_float2(v0, v1);
                    }
                }
            }
    }
#undef LOAD_A
#undef STORE_A
#undef LOAD_B
#undef STORE_B
}

// ---------------------------------------------------------------------------
// Dual bf16 GEMM (fused lin + g per layer), BN=64, BK=16:
//   C = leaky( (leaky(A2) @ W2^T) + b2 + leaky(A1 @ W1^T + b1) + id )
// W1, W2 fp32 [n][k]; A1 (x) and A2 (h) fp32, converted at smem store.
// ---------------------------------------------------------------------------
__global__ __launch_bounds__(256) void dual_gemm(
    const float* __restrict__ A1, const float* __restrict__ A2,
    const float* __restrict__ W1, const float* __restrict__ W2,
    const float* __restrict__ b1, const float* __restrict__ b2,
    const float* __restrict__ id_emb, float* __restrict__ C,
    int M, int K)
{
    constexpr int BM = 128, BN = 64, BK = 16, SW = 12;
    constexpr int WM = 32, MT = 2, NT = 4;     // warps 4x2

    __shared__ unsigned sA1[2][BM * SW];
    __shared__ unsigned sA2[2][BM * SW];
    __shared__ unsigned sB [2][2 * BN * SW];   // rows 0-63: W1, 64-127: W2

    const int t    = threadIdx.x;
    const int wid  = t >> 5;
    const int lane = t & 31;
    const int gid  = lane >> 2;
    const int tidg = lane & 3;
    const int wm   = (wid & 3) * WM;
    const int wn   = (wid >> 2) * 32;
    const int m0   = blockIdx.x * BM;

    float4 a1Reg[2], a2Reg[2], bReg[2];

    float acc1[MT][NT][4], acc2[MT][NT][4];
#pragma unroll
    for (int i = 0; i < MT; i++)
#pragma unroll
        for (int j = 0; j < NT; j++)
#pragma unroll
            for (int q = 0; q < 4; q++) { acc1[i][j][q] = 0.f; acc2[i][j][q] = 0.f; }

#define DLOAD(K0)                                                             \
    _Pragma("unroll")                                                         \
    for (int i = 0; i < 2; i++) {                                             \
        int fid = t + i * 256;                                                \
        int r = fid >> 2, k4 = fid & 3;                                       \
        int row = m0 + r;                                                     \
        float4 va = make_float4(0.f, 0.f, 0.f, 0.f);                          \
        float4 vb = make_float4(0.f, 0.f, 0.f, 0.f);                          \
        if (row < M) {                                                        \
            va = *(const float4*)&A1[(size_t)row * K + (K0) + k4 * 4];        \
            vb = *(const float4*)&A2[(size_t)row * K + (K0) + k4 * 4];        \
        }                                                                     \
        a1Reg[i] = va; a2Reg[i] = vb;                                         \
        const float* Wp = (r < BN) ? &W1[(size_t)r * K]                       \
                                   : &W2[(size_t)(r - BN) * K];               \
        bReg[i] = *(const float4*)&Wp[(K0) + k4 * 4];                         \
    }

#define DSTORE(BUF)                                                           \
    _Pragma("unroll")                                                         \
    for (int i = 0; i < 2; i++) {                                             \
        int fid = t + i * 256;                                                \
        int r = fid >> 2, k4 = fid & 3;                                       \
        float4 v = a1Reg[i];                                                  \
        *(uint2*)&sA1[BUF][r * SW + k4 * 2] =                                 \
            make_uint2(f2bf2(v.x, v.y), f2bf2(v.z, v.w));                     \
        v = a2Reg[i];                                                         \
        *(uint2*)&sA2[BUF][r * SW + k4 * 2] =                                 \
            make_uint2(f2bf2(leaky_(v.x), leaky_(v.y)),                       \
                       f2bf2(leaky_(v.z), leaky_(v.w)));                      \
        v = bReg[i];                                                          \
        *(uint2*)&sB[BUF][r * SW + k4 * 2] =                                  \
            make_uint2(f2bf2(v.x, v.y), f2bf2(v.z, v.w));                     \
    }

    const int nk = K / BK;
    DLOAD(0); DSTORE(0);
    __syncthreads();

    for (int it = 0; it < nk; it++) {
        const int buf = it & 1;
        if (it + 1 < nk) DLOAD((it + 1) * BK);

        unsigned af1[MT][4], af2[MT][4];
#pragma unroll
        for (int mt = 0; mt < MT; mt++) {
            int base = (wm + mt * 16 + gid) * SW;
            af1[mt][0] = sA1[buf][base + tidg];
            af1[mt][1] = sA1[buf][base + 8 * SW + tidg];
            af1[mt][2] = sA1[buf][base + tidg + 4];
            af1[mt][3] = sA1[buf][base + 8 * SW + tidg + 4];
            af2[mt][0] = sA2[buf][base + tidg];
            af2[mt][1] = sA2[buf][base + 8 * SW + tidg];
            af2[mt][2] = sA2[buf][base + tidg + 4];
            af2[mt][3] = sA2[buf][base + 8 * SW + tidg + 4];
        }
        unsigned bf1[NT][2], bf2[NT][2];
#pragma unroll
        for (int nt = 0; nt < NT; nt++) {
            int n = wn + nt * 8 + gid;
            bf1[nt][0] = sB[buf][n * SW + tidg];
            bf1[nt][1] = sB[buf][n * SW + tidg + 4];
            bf2[nt][0] = sB[buf][(n + BN) * SW + tidg];
            bf2[nt][1] = sB[buf][(n + BN) * SW + tidg + 4];
        }
#pragma unroll
        for (int mt = 0; mt < MT; mt++)
#pragma unroll
            for (int nt = 0; nt < NT; nt++) {
                mma_bf16(acc1[mt][nt], af1[mt], bf1[nt]);
                mma_bf16(acc2[mt][nt], af2[mt], bf2[nt]);
            }

        if (it + 1 < nk) {
            DSTORE(buf ^ 1);
            __syncthreads();
        }
    }

#pragma unroll
    for (int mt = 0; mt < MT; mt++)
#pragma unroll
        for (int nt = 0; nt < NT; nt++) {
            int col = wn + nt * 8 + 2 * tidg;
#pragma unroll
            for (int half = 0; half < 2; half++) {
                int row = m0 + wm + mt * 16 + gid + half * 8;
                if (row >= M) continue;
                float xh0 = leaky_(acc1[mt][nt][half * 2 + 0] + b1[col])
                          + id_emb[(size_t)row * BN + col];
                float xh1 = leaky_(acc1[mt][nt][half * 2 + 1] + b1[col + 1])
                          + id_emb[(size_t)row * BN + col + 1];
                float v0 = leaky_(acc2[mt][nt][half * 2 + 0] + b2[col] + xh0);
                float v1 = leaky_(acc2[mt][nt][half * 2 + 1] + b2[col + 1] + xh1);
                *(float2*)&C[(size_t)row * BN + col] = make_float2(v0, v1);
            }
        }
#undef DLOAD
#undef DSTORE
}

// ---------------------------------------------------------------------------
// Weight transpose + bf16 convert: src [Kdim][Ndim] fp32 -> dst [Ndim][Kdim] bf16
// ---------------------------------------------------------------------------
__global__ void transpose_cvt(const float* __restrict__ src,
                              __nv_bfloat16* __restrict__ dst, int Kdim, int Ndim)
{
    int i = blockIdx.x * 256 + threadIdx.x;
    if (i < Kdim * Ndim) {
        int k = i / Ndim, n = i % Ndim;
        dst[(size_t)n * Kdim + k] = __float2bfloat16(src[i]);
    }
}

// ---------------------------------------------------------------------------
// Fused copy + row-wise L2 normalize for preference rows (D=128, warp/row)
// ---------------------------------------------------------------------------
__global__ void pref_norm_kernel(const float* __restrict__ src,
                                 float* __restrict__ dst, int nrows)
{
    int warp = (blockIdx.x * blockDim.x + threadIdx.x) >> 5;
    int lane = threadIdx.x & 31;
    if (warp >= nrows) return;
    float4 v = *(const float4*)&src[(size_t)warp * 128 + lane * 4];
    float ss = v.x * v.x + v.y * v.y + v.z * v.z + v.w * v.w;
#pragma unroll
    for (int o = 16; o; o >>= 1) ss += __shfl_xor_sync(0xffffffffu, ss, o);
    float inv = 1.0f / fmaxf(sqrtf(ss), 1e-12f);
    v.x *= inv; v.y *= inv; v.z *= inv; v.w *= inv;
    *(float4*)&dst[(size_t)warp * 128 + lane * 4] = v;
}

// ---------------------------------------------------------------------------
// CSR build: histogram of dst, 3-phase exclusive scan, src reorder by dst
// ---------------------------------------------------------------------------
__global__ void hist_kernel(const int* __restrict__ ei, int* __restrict__ cnt)
{
    int e = blockIdx.x * blockDim.x + threadIdx.x;
    if (e < NE_) atomicAdd(&cnt[__ldg(&ei[NE_ + e])], 1);
}

__global__ void scan1_kernel(const int* __restrict__ in, int* __restrict__ out,
                             int* __restrict__ part, int n)
{
    __shared__ int s[1024];
    int i = blockIdx.x * 1024 + threadIdx.x;
    int v = (i < n) ? in[i] : 0;
    s[threadIdx.x] = v;
    __syncthreads();
#pragma unroll
    for (int o = 1; o < 1024; o <<= 1) {
        int y = (threadIdx.x >= o) ? s[threadIdx.x - o] : 0;
        __syncthreads();
        s[threadIdx.x] += y;
        __syncthreads();
    }
    if (i < n) out[i] = s[threadIdx.x] - v;
    if (threadIdx.x == 1023) part[blockIdx.x] = s[1023];
}

__global__ void scan2_kernel(int* __restrict__ part, int nb)
{
    __shared__ int s[128];
    int v = (threadIdx.x < nb) ? part[threadIdx.x] : 0;
    s[threadIdx.x] = v;
    __syncthreads();
#pragma unroll
    for (int o = 1; o < 128; o <<= 1) {
        int y = (threadIdx.x >= o) ? s[threadIdx.x - o] : 0;
        __syncthreads();
        s[threadIdx.x] += y;
        __syncthreads();
    }
    if (threadIdx.x < nb) part[threadIdx.x] = s[threadIdx.x] - v;  // exclusive
}

__global__ void scan3_kernel(int* __restrict__ out, const int* __restrict__ part, int n)
{
    int i = blockIdx.x * 1024 + threadIdx.x;
    if (i < n) out[i] += part[blockIdx.x];
}

__global__ void reorder_kernel(const int* __restrict__ ei, int* __restrict__ pos,
                               int* __restrict__ srcs)
{
    int e = blockIdx.x * blockDim.x + threadIdx.x;
    if (e >= NE_) return;
    int d = __ldg(&ei[NE_ + e]);
    int idx = atomicAdd(&pos[d], 1);
    srcs[idx] = __ldg(&ei[e]);
}

// ---------------------------------------------------------------------------
// Atomic-free segmented scatter over bf16 xw (16B lanes):
//   h[d] = sum_{e: dst=d} float(xw[srcs[e]])
// ---------------------------------------------------------------------------
template <int D>
__global__ void seg_scatter(const __nv_bfloat16* __restrict__ xw,
                            const int* __restrict__ offs,
                            const int* __restrict__ srcs,
                            float* __restrict__ h)
{
    constexpr int G = D / 8;       // 16B (8 bf16) chunks per row
    int gt   = blockIdx.x * blockDim.x + threadIdx.x;
    int node = gt / G;
    int q    = threadIdx.x % G;
    if (node >= NN_) return;

    int s   = __ldg(&offs[node]);
    int end = __ldg(&offs[node + 1]);

    float a[8] = {0,0,0,0,0,0,0,0};
    float b[8] = {0,0,0,0,0,0,0,0};

#define ACC8(dst, u)                                                        \
    {                                                                       \
        float2 f;                                                           \
        f = __bfloat1622float2(*(const __nv_bfloat162*)&(u).x);             \
        dst[0] += f.x; dst[1] += f.y;                                       \
        f = __bfloat1622float2(*(const __nv_bfloat162*)&(u).y);             \
        dst[2] += f.x; dst[3] += f.y;                                       \
        f = __bfloat1622float2(*(const __nv_bfloat162*)&(u).z);             \
        dst[4] += f.x; dst[5] += f.y;                                       \
        f = __bfloat1622float2(*(const __nv_bfloat162*)&(u).w);             \
        dst[6] += f.x; dst[7] += f.y;                                       \
    }

    int i = s;
    for (; i + 3 < end; i += 4) {
        int s0 = __ldg(&srcs[i + 0]);
        int s1 = __ldg(&srcs[i + 1]);
        int s2 = __ldg(&srcs[i + 2]);
        int s3 = __ldg(&srcs[i + 3]);
        uint4 u0 = *(const uint4*)&xw[(size_t)s0 * D + q * 8];
        uint4 u1 = *(const uint4*)&xw[(size_t)s1 * D + q * 8];
        uint4 u2 = *(const uint4*)&xw[(size_t)s2 * D + q * 8];
        uint4 u3 = *(const uint4*)&xw[(size_t)s3 * D + q * 8];
        ACC8(a, u0); ACC8(b, u1); ACC8(a, u2); ACC8(b, u3);
    }
    for (; i < end; i++) {
        int s0 = __ldg(&srcs[i]);
        uint4 u0 = *(const uint4*)&xw[(size_t)s0 * D + q * 8];
        ACC8(a, u0);
    }
#undef ACC8

    float4 r0 = make_float4(a[0] + b[0], a[1] + b[1], a[2] + b[2], a[3] + b[3]);
    float4 r1 = make_float4(a[4] + b[4], a[5] + b[5], a[6] + b[6], a[7] + b[7]);
    *(float4*)&h[(size_t)node * D + q * 8]     = r0;
    *(float4*)&h[(size_t)node * D + q * 8 + 4] = r1;
}

// ---------------------------------------------------------------------------
extern "C" void kernel_launch(void* const* d_in, const int* in_sizes, int n_in,
                              void* d_out, int out_size)
{
    const float* features = (const float*)d_in[0];
    const float* id_emb   = (const float*)d_in[1];
    const float* pref     = (const float*)d_in[2];
    const float* mlp_w    = (const float*)d_in[3];
    const float* mlp_b    = (const float*)d_in[4];
    const float* conv1_w  = (const float*)d_in[5];
    const float* lin1_w   = (const float*)d_in[6];
    const float* lin1_b   = (const float*)d_in[7];
    const float* g1_w     = (const float*)d_in[8];
    const float* g1_b     = (const float*)d_in[9];
    const float* conv2_w  = (const float*)d_in[10];
    const float* lin2_w   = (const float*)d_in[11];
    const float* lin2_b   = (const float*)d_in[12];
    const float* g2_w     = (const float*)d_in[13];
    const float* g2_b     = (const float*)d_in[14];
    const int*   ei       = (const int*)d_in[15];
    float* out = (float*)d_out;

    float *px, *ph, *px2;
    __nv_bfloat16 *pxw, *pwc1, *pwc2;
    int *pcnt, *poffs, *ppart, *ppos, *psrcs;
    cudaGetSymbolAddress((void**)&px,    g_x);
    cudaGetSymbolAddress((void**)&pxw,   g_xw);
    cudaGetSymbolAddress((void**)&ph,    g_h);
    cudaGetSymbolAddress((void**)&px2,   g_x2);
    cudaGetSymbolAddress((void**)&pwc1,  g_wc1);
    cudaGetSymbolAddress((void**)&pwc2,  g_wc2);
    cudaGetSymbolAddress((void**)&pcnt,  g_cnt);
    cudaGetSymbolAddress((void**)&poffs, g_offs);
    cudaGetSymbolAddress((void**)&ppart, g_part);
    cudaGetSymbolAddress((void**)&ppos,  g_pos);
    cudaGetSymbolAddress((void**)&psrcs, g_srcs);

    const int GB_N  = (NN_ + 127) / 128;
    const int NSCAN = NN_ + 1;
    const int NBLK  = (NSCAN + 1023) / 1024;

    static cudaStream_t s_csr = nullptr;
    static cudaEvent_t ev_fork = nullptr, ev_join = nullptr;
    if (!s_csr) {
        cudaStreamCreateWithFlags(&s_csr, cudaStreamNonBlocking);
        cudaEventCreateWithFlags(&ev_fork, cudaEventDisableTiming);
        cudaEventCreateWithFlags(&ev_join, cudaEventDisableTiming);
    }

    // ---- fork: CSR build + weight prep + pref_norm on side stream ----
    cudaEventRecord(ev_fork, 0);
    cudaStreamWaitEvent(s_csr, ev_fork, 0);
    cudaMemsetAsync(pcnt, 0, NSCAN * sizeof(int), s_csr);
    hist_kernel<<<(NE_ + 255) / 256, 256, 0, s_csr>>>(ei, pcnt);
    scan1_kernel<<<NBLK, 1024, 0, s_csr>>>(pcnt, poffs, ppart, NSCAN);
    scan2_kernel<<<1, 128, 0, s_csr>>>(ppart, NBLK);
    scan3_kernel<<<NBLK, 1024, 0, s_csr>>>(poffs, ppart, NSCAN);
    cudaMemcpyAsync(ppos, poffs, NN_ * sizeof(int), cudaMemcpyDeviceToDevice, s_csr);
    reorder_kernel<<<(NE_ + 255) / 256, 256, 0, s_csr>>>(ei, ppos, psrcs);
    transpose_cvt<<<(DL_ * DL_ + 255) / 256, 256, 0, s_csr>>>(conv1_w, pwc1, DL_, DL_);
    transpose_cvt<<<(DI_ * DI_ + 255) / 256, 256, 0, s_csr>>>(conv2_w, pwc2, DI_, DI_);
    pref_norm_kernel<<<(NU_ * 32 + 255) / 256, 256, 0, s_csr>>>(pref, px, NU_);
    cudaEventRecord(ev_join, s_csr);

    // ---- main stream ----
    // x[NU:] = normalize(features @ mlp_w^T + mlp_b)   (bf16 mma)
    mma_gemm<128, true, false, false><<<(NI_ + 127) / 128, 256>>>(
        features, mlp_w, px + (size_t)NU_ * DL_, NI_, DF_, mlp_b);
    cudaStreamWaitEvent(0, ev_join, 0);   // join: pref rows + CSR + weights ready

    // ===== layer 1 =====
    mma_gemm<128, false, true, true><<<GB_N, 256>>>(
        px, pwc1, pxw, NN_, DL_, nullptr);
    seg_scatter<128><<<(NN_ * 16 + 255) / 256, 256>>>(pxw, poffs, psrcs, ph);
    dual_gemm<<<GB_N, 256>>>(px, ph, lin1_w, g1_w, lin1_b, g1_b, id_emb, px2, NN_, DL_);

    // ===== layer 2 =====
    mma_gemm<64, false, true, true><<<GB_N, 256>>>(
        px2, pwc2, pxw, NN_, DI_, nullptr);
    seg_scatter<64><<<(NN_ * 8 + 255) / 256, 256>>>(pxw, poffs, psrcs, ph);
    dual_gemm<<<GB_N, 256>>>(px2, ph, lin2_w, g2_w, lin2_b, g2_b, id_emb, out, NN_, DI_);
}

// round 12
// speedup vs baseline: 1.2847x; 1.0002x over previous
#include <cuda_runtime.h>
#include <cuda_bf16.h>
#include <math.h>

// Problem constants (fixed shapes per reference)
#define NU_  40000
#define NI_  60000
#define NN_  100000
#define DF_  1024
#define DL_  128
#define DI_  64
#define NE_  1600000

// Scratch buffers (device globals: allocation-guard safe)
__device__ __align__(16) __nv_bfloat16 g_x [(size_t)NN_ * DL_];  // x (bf16)
__device__ __align__(16) __nv_bfloat16 g_xw[(size_t)NN_ * DL_];  // conv out (bf16)
__device__ float g_h   [(size_t)NN_ * DL_];                      // segment sum fp32
__device__ __align__(16) __nv_bfloat16 g_x2[(size_t)NN_ * DI_];  // layer-1 out (bf16)
__device__ float g_xhat[(size_t)NN_ * DI_];                      // lin output fp32
// bf16 transposed weight copies (built on side stream)
__device__ __align__(16) __nv_bfloat16 g_wc1[DL_ * DL_];  // conv1_w^T [n][k]
__device__ __align__(16) __nv_bfloat16 g_wc2[DI_ * DI_];  // conv2_w^T [n][k]
// CSR build scratch
__device__ int g_cnt [NN_ + 1];
__device__ int g_offs[NN_ + 1];
__device__ int g_part[128];
__device__ int g_pos [NN_];
__device__ int g_srcs[NE_];

#define MODE_NORM  0   // v = acc + bias; row L2 norm
#define MODE_PLAIN 1   // v = acc
#define MODE_LIN   2   // v = leaky(acc + bias) + aux[row,col]
#define MODE_G     3   // A gets leaky at fill; v = leaky(acc + bias + aux[row,col])

__device__ __forceinline__ float leaky_(float v) { return v > 0.0f ? v : 0.01f * v; }

__device__ __forceinline__ unsigned f2bf2(float lo, float hi) {
    __nv_bfloat162 h = __floats2bfloat162_rn(lo, hi);
    return *reinterpret_cast<unsigned*>(&h);
}

// bf16 m16n8k16 mma, fp32 accumulate
__device__ __forceinline__ void mma_bf16(float* d, const unsigned* a, const unsigned* b) {
    asm volatile(
        "mma.sync.aligned.m16n8k16.row.col.f32.bf16.bf16.f32 "
        "{%0,%1,%2,%3}, {%4,%5,%6,%7}, {%8,%9}, {%0,%1,%2,%3};"
        : "+f"(d[0]), "+f"(d[1]), "+f"(d[2]), "+f"(d[3])
        : "r"(a[0]), "r"(a[1]), "r"(a[2]), "r"(a[3]), "r"(b[0]), "r"(b[1]));
}

// ---------------------------------------------------------------------------
// Unified bf16 tensor-core GEMM: C[M,BN] = op(A[M,K]) @ B[BN,K]^T
//   ABF16: A is bf16 in gmem (direct smem copy); else fp32 (cvt at fill,
//          +leaky when MODE_G)
//   BBF16: B is bf16 in gmem; else fp32 (cvt at fill)
//   OUTBF16: bf16 output; else fp32
// BM=128, BK=16 double-buffered (register staged), 256 threads.
// smem bf16 packed 2/word, row stride SW=12 words (conflict-free frag LDS).
// ---------------------------------------------------------------------------
template <int BN, int MODE, bool ABF16, bool OUTBF16, bool BBF16>
__global__ __launch_bounds__(256) void mma_gemm(
    const void* __restrict__ Av, const void* __restrict__ Bv,
    void* __restrict__ Cv, int M, int K,
    const float* __restrict__ bias, const float* __restrict__ aux)
{
    constexpr int BM = 128, BK = 16, SW = 12;
    constexpr int WARPS_M = (BN == 128) ? 2 : 4;
    constexpr int WM = BM / WARPS_M;
    constexpr int MT = WM / 16;
    constexpr int NT = 4;

    __shared__ unsigned sA[2][BM * SW];
    __shared__ unsigned sB[2][BN * SW];
    __shared__ float sNorm[(MODE == MODE_NORM) ? BM : 1];

    const int t    = threadIdx.x;
    const int wid  = t >> 5;
    const int lane = t & 31;
    const int gid  = lane >> 2;
    const int tidg = lane & 3;
    const int wm   = (wid % WARPS_M) * WM;
    const int wn   = (wid / WARPS_M) * 32;
    const int m0   = blockIdx.x * BM;

    float4 aRegF[2];
    uint4  aRegV;
    float4 bRegF[2];
    uint4  bRegV4;
    uint2  bRegV2;

    float acc[MT][NT][4];
#pragma unroll
    for (int i = 0; i < MT; i++)
#pragma unroll
        for (int j = 0; j < NT; j++)
#pragma unroll
            for (int q = 0; q < 4; q++) acc[i][j][q] = 0.0f;

#define LOAD_A(K0)                                                            \
    if (ABF16) {                                                              \
        const __nv_bfloat16* Ab = (const __nv_bfloat16*)Av;                   \
        int r = t >> 1, h = t & 1;                                            \
        int row = m0 + r;                                                     \
        aRegV = make_uint4(0u, 0u, 0u, 0u);                                   \
        if (row < M) aRegV = *(const uint4*)&Ab[(size_t)row * K + (K0) + h*8];\
    } else {                                                                  \
        const float* Af = (const float*)Av;                                   \
        _Pragma("unroll")                                                     \
        for (int i = 0; i < 2; i++) {                                         \
            int fid = t + i * 256;                                            \
            int r = fid >> 2, k4 = fid & 3;                                   \
            int row = m0 + r;                                                 \
            float4 v = make_float4(0.f, 0.f, 0.f, 0.f);                       \
            if (row < M) v = *(const float4*)&Af[(size_t)row*K + (K0) + k4*4];\
            aRegF[i] = v;                                                     \
        }                                                                     \
    }

#define STORE_A(BUF)                                                          \
    if (ABF16) {                                                              \
        int r = t >> 1, h = t & 1;                                            \
        *(uint4*)&sA[BUF][r * SW + h * 4] = aRegV;                            \
    } else {                                                                  \
        _Pragma("unroll")                                                     \
        for (int i = 0; i < 2; i++) {                                         \
            int fid = t + i * 256;                                            \
            int r = fid >> 2, k4 = fid & 3;                                   \
            float4 v = aRegF[i];                                              \
            if (MODE == MODE_G) {                                             \
                v.x = leaky_(v.x); v.y = leaky_(v.y);                         \
                v.z = leaky_(v.z); v.w = leaky_(v.w);                         \
            }                                                                 \
            uint2 u = make_uint2(f2bf2(v.x, v.y), f2bf2(v.z, v.w));           \
            *(uint2*)&sA[BUF][r * SW + k4 * 2] = u;                           \
        }                                                                     \
    }

#define LOAD_B(K0)                                                            \
    if (BBF16) {                                                              \
        const __nv_bfloat16* Bb = (const __nv_bfloat16*)Bv;                   \
        if (BN == 128) {                                                      \
            int n = t >> 1, h = t & 1;                                        \
            bRegV4 = *(const uint4*)&Bb[(size_t)n * K + (K0) + h * 8];        \
        } else {                                                              \
            int n = t >> 2, q = t & 3;                                        \
            bRegV2 = *(const uint2*)&Bb[(size_t)n * K + (K0) + q * 4];        \
        }                                                                     \
    } else {                                                                  \
        const float* Bf = (const float*)Bv;                                   \
        if (BN == 128) {                                                      \
            _Pragma("unroll")                                                 \
            for (int i = 0; i < 2; i++) {                                     \
                int fid = t + i * 256;                                        \
                int n = fid >> 2, k4 = fid & 3;                               \
                bRegF[i] = *(const float4*)&Bf[(size_t)n * K + (K0) + k4*4];  \
            }                                                                 \
        } else {                                                              \
            int n = t >> 2, k4 = t & 3;                                       \
            bRegF[0] = *(const float4*)&Bf[(size_t)n * K + (K0) + k4 * 4];    \
        }                                                                     \
    }

#define STORE_B(BUF)                                                          \
    if (BBF16) {                                                              \
        if (BN == 128) {                                                      \
            int n = t >> 1, h = t & 1;                                        \
            *(uint4*)&sB[BUF][n * SW + h * 4] = bRegV4;                       \
        } else {                                                              \
            int n = t >> 2, q = t & 3;                                        \
            *(uint2*)&sB[BUF][n * SW + q * 2] = bRegV2;                       \
        }                                                                     \
    } else {                                                                  \
        if (BN == 128) {                                                      \
            _Pragma("unroll")                                                 \
            for (int i = 0; i < 2; i++) {                                     \
                int fid = t + i * 256;                                        \
                int n = fid >> 2, k4 = fid & 3;                               \
                float4 v = bRegF[i];                                          \
                uint2 u = make_uint2(f2bf2(v.x, v.y), f2bf2(v.z, v.w));       \
                *(uint2*)&sB[BUF][n * SW + k4 * 2] = u;                       \
            }                                                                 \
        } else {                                                              \
            int n = t >> 2, k4 = t & 3;                                       \
            float4 v = bRegF[0];                                              \
            uint2 u = make_uint2(f2bf2(v.x, v.y), f2bf2(v.z, v.w));           \
            *(uint2*)&sB[BUF][n * SW + k4 * 2] = u;                           \
        }                                                                     \
    }

    const int nk = K / BK;
    LOAD_A(0); LOAD_B(0);
    STORE_A(0); STORE_B(0);
    __syncthreads();

    for (int it = 0; it < nk; it++) {
        const int buf = it & 1;
        if (it + 1 < nk) { LOAD_A((it + 1) * BK); LOAD_B((it + 1) * BK); }

        unsigned af[MT][4];
#pragma unroll
        for (int mt = 0; mt < MT; mt++) {
            int base = (wm + mt * 16 + gid) * SW;
            af[mt][0] = sA[buf][base + tidg];
            af[mt][1] = sA[buf][base + 8 * SW + tidg];
            af[mt][2] = sA[buf][base + tidg + 4];
            af[mt][3] = sA[buf][base + 8 * SW + tidg + 4];
        }
        unsigned bf[NT][2];
#pragma unroll
        for (int nt = 0; nt < NT; nt++) {
            int nb = (wn + nt * 8 + gid) * SW;
            bf[nt][0] = sB[buf][nb + tidg];
            bf[nt][1] = sB[buf][nb + tidg + 4];
        }
#pragma unroll
        for (int mt = 0; mt < MT; mt++)
#pragma unroll
            for (int nt = 0; nt < NT; nt++)
                mma_bf16(acc[mt][nt], af[mt], bf[nt]);

        if (it + 1 < nk) {
            STORE_A(buf ^ 1); STORE_B(buf ^ 1);
            __syncthreads();
        }
    }

    // ---- epilogue ----
    if (MODE == MODE_NORM) {
        if (t < BM) sNorm[t] = 0.0f;
        __syncthreads();
#pragma unroll
        for (int mt = 0; mt < MT; mt++)
#pragma unroll
            for (int nt = 0; nt < NT; nt++) {
                int col = wn + nt * 8 + 2 * tidg;
#pragma unroll
                for (int half = 0; half < 2; half++) {
                    int rl = wm + mt * 16 + gid + half * 8;
                    if (m0 + rl >= M) continue;
                    float v0 = acc[mt][nt][half * 2 + 0] + bias[col];
                    float v1 = acc[mt][nt][half * 2 + 1] + bias[col + 1];
                    acc[mt][nt][half * 2 + 0] = v0;
                    acc[mt][nt][half * 2 + 1] = v1;
                    atomicAdd(&sNorm[rl], v0 * v0 + v1 * v1);
                }
            }
        __syncthreads();
        if (t < BM) sNorm[t] = 1.0f / fmaxf(sqrtf(sNorm[t]), 1e-12f);
        __syncthreads();
    }

#pragma unroll
    for (int mt = 0; mt < MT; mt++)
#pragma unroll
        for (int nt = 0; nt < NT; nt++) {
            int col = wn + nt * 8 + 2 * tidg;
#pragma unroll
            for (int half = 0; half < 2; half++) {
                int rl = wm + mt * 16 + gid + half * 8;
                int row = m0 + rl;
                if (row >= M) continue;
                float v0 = acc[mt][nt][half * 2 + 0];
                float v1 = acc[mt][nt][half * 2 + 1];
                if (MODE == MODE_NORM) {
                    float inv = sNorm[rl];
                    v0 = (v0)*inv; v1 = (v1)*inv;
                } else if (MODE == MODE_LIN) {
                    v0 = leaky_(v0 + bias[col]) + aux[(size_t)row * BN + col];
                    v1 = leaky_(v1 + bias[col + 1]) + aux[(size_t)row * BN + col + 1];
                } else if (MODE == MODE_G) {
                    v0 = leaky_(v0 + bias[col] + aux[(size_t)row * BN + col]);
                    v1 = leaky_(v1 + bias[col + 1] + aux[(size_t)row * BN + col + 1]);
                }
                if (OUTBF16) {
                    __nv_bfloat16* C = (__nv_bfloat16*)Cv;
                    *(__nv_bfloat162*)&C[(size_t)row * BN + col] =
                        __floats2bfloat162_rn(v0, v1);
                } else {
                    float* C = (float*)Cv;
                    *(float2*)&C[(size_t)row * BN + col] = make_float2(v0, v1);
                }
            }
        }
#undef LOAD_A
#undef STORE_A
#undef LOAD_B
#undef STORE_B
}

// ---------------------------------------------------------------------------
// Weight transpose + bf16 convert: src [Kdim][Ndim] fp32 -> dst [Ndim][Kdim] bf16
// ---------------------------------------------------------------------------
__global__ void transpose_cvt(const float* __restrict__ src,
                              __nv_bfloat16* __restrict__ dst, int Kdim, int Ndim)
{
    int i = blockIdx.x * 256 + threadIdx.x;
    if (i < Kdim * Ndim) {
        int k = i / Ndim, n = i % Ndim;
        dst[(size_t)n * Kdim + k] = __float2bfloat16(src[i]);
    }
}

// ---------------------------------------------------------------------------
// Fused copy + row-wise L2 normalize for preference rows; bf16 output
// ---------------------------------------------------------------------------
__global__ void pref_norm_kernel(const float* __restrict__ src,
                                 __nv_bfloat16* __restrict__ dst, int nrows)
{
    int warp = (blockIdx.x * blockDim.x + threadIdx.x) >> 5;
    int lane = threadIdx.x & 31;
    if (warp >= nrows) return;
    float4 v = *(const float4*)&src[(size_t)warp * 128 + lane * 4];
    float ss = v.x * v.x + v.y * v.y + v.z * v.z + v.w * v.w;
#pragma unroll
    for (int o = 16; o; o >>= 1) ss += __shfl_xor_sync(0xffffffffu, ss, o);
    float inv = 1.0f / fmaxf(sqrtf(ss), 1e-12f);
    uint2 u = make_uint2(f2bf2(v.x * inv, v.y * inv), f2bf2(v.z * inv, v.w * inv));
    *(uint2*)&dst[(size_t)warp * 128 + lane * 4] = u;
}

// ---------------------------------------------------------------------------
// CSR build: histogram of dst, 3-phase exclusive scan, src reorder by dst
// ---------------------------------------------------------------------------
__global__ void hist_kernel(const int* __restrict__ ei, int* __restrict__ cnt)
{
    int e = blockIdx.x * blockDim.x + threadIdx.x;
    if (e < NE_) atomicAdd(&cnt[__ldg(&ei[NE_ + e])], 1);
}

__global__ void scan1_kernel(const int* __restrict__ in, int* __restrict__ out,
                             int* __restrict__ part, int n)
{
    __shared__ int s[1024];
    int i = blockIdx.x * 1024 + threadIdx.x;
    int v = (i < n) ? in[i] : 0;
    s[threadIdx.x] = v;
    __syncthreads();
#pragma unroll
    for (int o = 1; o < 1024; o <<= 1) {
        int y = (threadIdx.x >= o) ? s[threadIdx.x - o] : 0;
        __syncthreads();
        s[threadIdx.x] += y;
        __syncthreads();
    }
    if (i < n) out[i] = s[threadIdx.x] - v;
    if (threadIdx.x == 1023) part[blockIdx.x] = s[1023];
}

__global__ void scan2_kernel(int* __restrict__ part, int nb)
{
    __shared__ int s[128];
    int v = (threadIdx.x < nb) ? part[threadIdx.x] : 0;
    s[threadIdx.x] = v;
    __syncthreads();
#pragma unroll
    for (int o = 1; o < 128; o <<= 1) {
        int y = (threadIdx.x >= o) ? s[threadIdx.x - o] : 0;
        __syncthreads();
        s[threadIdx.x] += y;
        __syncthreads();
    }
    if (threadIdx.x < nb) part[threadIdx.x] = s[threadIdx.x] - v;  // exclusive
}

__global__ void scan3_kernel(int* __restrict__ out, const int* __restrict__ part, int n)
{
    int i = blockIdx.x * 1024 + threadIdx.x;
    if (i < n) out[i] += part[blockIdx.x];
}

__global__ void reorder_kernel(const int* __restrict__ ei, int* __restrict__ pos,
                               int* __restrict__ srcs)
{
    int e = blockIdx.x * blockDim.x + threadIdx.x;
    if (e >= NE_) return;
    int d = __ldg(&ei[NE_ + e]);
    int idx = atomicAdd(&pos[d], 1);
    srcs[idx] = __ldg(&ei[e]);
}

// ---------------------------------------------------------------------------
// Atomic-free segmented scatter over bf16 xw (16B lanes):
//   h[d] = sum_{e: dst=d} float(xw[srcs[e]])   (fp32 out)
// ---------------------------------------------------------------------------
template <int D>
__global__ void seg_scatter(const __nv_bfloat16* __restrict__ xw,
                            const int* __restrict__ offs,
                            const int* __restrict__ srcs,
                            float* __restrict__ h)
{
    constexpr int G = D / 8;
    int gt   = blockIdx.x * blockDim.x + threadIdx.x;
    int node = gt / G;
    int q    = threadIdx.x % G;
    if (node >= NN_) return;

    int s   = __ldg(&offs[node]);
    int end = __ldg(&offs[node + 1]);

    float a[8] = {0,0,0,0,0,0,0,0};
    float b[8] = {0,0,0,0,0,0,0,0};

#define ACC8(dst, u)                                                        \
    {                                                                       \
        float2 f;                                                           \
        f = __bfloat1622float2(*(const __nv_bfloat162*)&(u).x);             \
        dst[0] += f.x; dst[1] += f.y;                                       \
        f = __bfloat1622float2(*(const __nv_bfloat162*)&(u).y);             \
        dst[2] += f.x; dst[3] += f.y;                                       \
        f = __bfloat1622float2(*(const __nv_bfloat162*)&(u).z);             \
        dst[4] += f.x; dst[5] += f.y;                                       \
        f = __bfloat1622float2(*(const __nv_bfloat162*)&(u).w);             \
        dst[6] += f.x; dst[7] += f.y;                                       \
    }

    int i = s;
    for (; i + 3 < end; i += 4) {
        int s0 = __ldg(&srcs[i + 0]);
        int s1 = __ldg(&srcs[i + 1]);
        int s2 = __ldg(&srcs[i + 2]);
        int s3 = __ldg(&srcs[i + 3]);
        uint4 u0 = *(const uint4*)&xw[(size_t)s0 * D + q * 8];
        uint4 u1 = *(const uint4*)&xw[(size_t)s1 * D + q * 8];
        uint4 u2 = *(const uint4*)&xw[(size_t)s2 * D + q * 8];
        uint4 u3 = *(const uint4*)&xw[(size_t)s3 * D + q * 8];
        ACC8(a, u0); ACC8(b, u1); ACC8(a, u2); ACC8(b, u3);
    }
    for (; i < end; i++) {
        int s0 = __ldg(&srcs[i]);
        uint4 u0 = *(const uint4*)&xw[(size_t)s0 * D + q * 8];
        ACC8(a, u0);
    }
#undef ACC8

    float4 r0 = make_float4(a[0] + b[0], a[1] + b[1], a[2] + b[2], a[3] + b[3]);
    float4 r1 = make_float4(a[4] + b[4], a[5] + b[5], a[6] + b[6], a[7] + b[7]);
    *(float4*)&h[(size_t)node * D + q * 8]     = r0;
    *(float4*)&h[(size_t)node * D + q * 8 + 4] = r1;
}

// ---------------------------------------------------------------------------
extern "C" void kernel_launch(void* const* d_in, const int* in_sizes, int n_in,
                              void* d_out, int out_size)
{
    const float* features = (const float*)d_in[0];
    const float* id_emb   = (const float*)d_in[1];
    const float* pref     = (const float*)d_in[2];
    const float* mlp_w    = (const float*)d_in[3];
    const float* mlp_b    = (const float*)d_in[4];
    const float* conv1_w  = (const float*)d_in[5];
    const float* lin1_w   = (const float*)d_in[6];
    const float* lin1_b   = (const float*)d_in[7];
    const float* g1_w     = (const float*)d_in[8];
    const float* g1_b     = (const float*)d_in[9];
    const float* conv2_w  = (const float*)d_in[10];
    const float* lin2_w   = (const float*)d_in[11];
    const float* lin2_b   = (const float*)d_in[12];
    const float* g2_w     = (const float*)d_in[13];
    const float* g2_b     = (const float*)d_in[14];
    const int*   ei       = (const int*)d_in[15];
    float* out = (float*)d_out;

    float *ph, *pxhat;
    __nv_bfloat16 *px, *pxw, *px2, *pwc1, *pwc2;
    int *pcnt, *poffs, *ppart, *ppos, *psrcs;
    cudaGetSymbolAddress((void**)&px,    g_x);
    cudaGetSymbolAddress((void**)&pxw,   g_xw);
    cudaGetSymbolAddress((void**)&ph,    g_h);
    cudaGetSymbolAddress((void**)&px2,   g_x2);
    cudaGetSymbolAddress((void**)&pxhat, g_xhat);
    cudaGetSymbolAddress((void**)&pwc1,  g_wc1);
    cudaGetSymbolAddress((void**)&pwc2,  g_wc2);
    cudaGetSymbolAddress((void**)&pcnt,  g_cnt);
    cudaGetSymbolAddress((void**)&poffs, g_offs);
    cudaGetSymbolAddress((void**)&ppart, g_part);
    cudaGetSymbolAddress((void**)&ppos,  g_pos);
    cudaGetSymbolAddress((void**)&psrcs, g_srcs);

    const int GB_N  = (NN_ + 127) / 128;
    const int NSCAN = NN_ + 1;
    const int NBLK  = (NSCAN + 1023) / 1024;

    static cudaStream_t s_side = nullptr;
    static cudaEvent_t ev_fork = nullptr, ev_join = nullptr, ev_mlp = nullptr,
                       ev_lin1 = nullptr, ev_g1 = nullptr, ev_lin2 = nullptr;
    if (!s_side) {
        cudaStreamCreateWithFlags(&s_side, cudaStreamNonBlocking);
        cudaEventCreateWithFlags(&ev_fork, cudaEventDisableTiming);
        cudaEventCreateWithFlags(&ev_join, cudaEventDisableTiming);
        cudaEventCreateWithFlags(&ev_mlp,  cudaEventDisableTiming);
        cudaEventCreateWithFlags(&ev_lin1, cudaEventDisableTiming);
        cudaEventCreateWithFlags(&ev_g1,   cudaEventDisableTiming);
        cudaEventCreateWithFlags(&ev_lin2, cudaEventDisableTiming);
    }

    // ---- fork: CSR build + weight prep + pref_norm on side stream ----
    cudaEventRecord(ev_fork, 0);
    cudaStreamWaitEvent(s_side, ev_fork, 0);
    cudaMemsetAsync(pcnt, 0, NSCAN * sizeof(int), s_side);
    hist_kernel<<<(NE_ + 255) / 256, 256, 0, s_side>>>(ei, pcnt);
    scan1_kernel<<<NBLK, 1024, 0, s_side>>>(pcnt, poffs, ppart, NSCAN);
    scan2_kernel<<<1, 128, 0, s_side>>>(ppart, NBLK);
    scan3_kernel<<<NBLK, 1024, 0, s_side>>>(poffs, ppart, NSCAN);
    cudaMemcpyAsync(ppos, poffs, NN_ * sizeof(int), cudaMemcpyDeviceToDevice, s_side);
    reorder_kernel<<<(NE_ + 255) / 256, 256, 0, s_side>>>(ei, ppos, psrcs);
    transpose_cvt<<<(DL_ * DL_ + 255) / 256, 256, 0, s_side>>>(conv1_w, pwc1, DL_, DL_);
    transpose_cvt<<<(DI_ * DI_ + 255) / 256, 256, 0, s_side>>>(conv2_w, pwc2, DI_, DI_);
    pref_norm_kernel<<<(NU_ * 32 + 255) / 256, 256, 0, s_side>>>(pref, px, NU_);
    cudaEventRecord(ev_join, s_side);

    // ---- main: MLP (x[NU:] = normalize(features @ mlp_w^T + mlp_b), bf16 out)
    mma_gemm<128, MODE_NORM, false, true, false><<<(NI_ + 127) / 128, 256>>>(
        features, mlp_w, px + (size_t)NU_ * DL_, NI_, DF_, mlp_b, nullptr);
    cudaEventRecord(ev_mlp, 0);
    cudaStreamWaitEvent(0, ev_join, 0);

    // side: lin1 (xhat = leaky(x@lin1^T+b)+id) overlapped with conv1+scatter
    cudaStreamWaitEvent(s_side, ev_mlp, 0);
    mma_gemm<64, MODE_LIN, true, false, false><<<GB_N, 256, 0, s_side>>>(
        px, lin1_w, pxhat, NN_, DL_, lin1_b, id_emb);
    cudaEventRecord(ev_lin1, s_side);

    // ===== layer 1 (main) =====
    mma_gemm<128, MODE_PLAIN, true, true, true><<<GB_N, 256>>>(
        px, pwc1, pxw, NN_, DL_, nullptr, nullptr);
    seg_scatter<128><<<(NN_ * 16 + 255) / 256, 256>>>(pxw, poffs, psrcs, ph);
    cudaStreamWaitEvent(0, ev_lin1, 0);
    // x2 = leaky(leaky(h)@g1^T + b + xhat)  -> bf16
    mma_gemm<64, MODE_G, false, true, false><<<GB_N, 256>>>(
        ph, g1_w, px2, NN_, DL_, g1_b, pxhat);
    cudaEventRecord(ev_g1, 0);

    // side: lin2 overlapped with conv2+scatter64
    cudaStreamWaitEvent(s_side, ev_g1, 0);
    mma_gemm<64, MODE_LIN, true, false, false><<<GB_N, 256, 0, s_side>>>(
        px2, lin2_w, pxhat, NN_, DI_, lin2_b, id_emb);
    cudaEventRecord(ev_lin2, s_side);

    // ===== layer 2 (main) =====
    mma_gemm<64, MODE_PLAIN, true, true, true><<<GB_N, 256>>>(
        px2, pwc2, pxw, NN_, DI_, nullptr, nullptr);
    seg_scatter<64><<<(NN_ * 8 + 255) / 256, 256>>>(pxw, poffs, psrcs, ph);
    cudaStreamWaitEvent(0, ev_lin2, 0);
    mma_gemm<64, MODE_G, false, false, false><<<GB_N, 256>>>(
        ph, g2_w, out, NN_, DI_, g2_b, pxhat);
}

// round 13
// speedup vs baseline: 1.3986x; 1.0887x over previous
#include <cuda_runtime.h>
#include <cuda_bf16.h>
#include <math.h>

// Problem constants (fixed shapes per reference)
#define NU_  40000
#define NI_  60000
#define NN_  100000
#define DF_  1024
#define DL_  128
#define DI_  64
#define NE_  1600000

// Scratch buffers (device globals: allocation-guard safe)
__device__ __align__(16) __nv_bfloat16 g_x [(size_t)NN_ * DL_];  // x (bf16)
__device__ __align__(16) __nv_bfloat16 g_xw[(size_t)NN_ * DL_];  // conv out (bf16)
__device__ float g_h   [(size_t)NN_ * DL_];                      // segment sum fp32
__device__ __align__(16) __nv_bfloat16 g_x2[(size_t)NN_ * DI_];  // layer-1 out (bf16)
__device__ float g_xhat[(size_t)NN_ * DI_];                      // lin output fp32
// bf16 transposed weight copies (built on side stream)
__device__ __align__(16) __nv_bfloat16 g_wc1[DL_ * DL_];  // conv1_w^T [n][k]
__device__ __align__(16) __nv_bfloat16 g_wc2[DI_ * DI_];  // conv2_w^T [n][k]
// CSR build scratch
__device__ int g_cnt [NN_ + 1];
__device__ int g_offs[NN_ + 1];
__device__ int g_part[128];
__device__ int g_pos [NN_];
__device__ int g_srcs[NE_];

#define MODE_NORM  0   // v = acc + bias; row L2 norm
#define MODE_PLAIN 1   // v = acc
#define MODE_LIN   2   // v = leaky(acc + bias) + aux[row,col]
#define MODE_G     3   // A gets leaky at fill; v = leaky(acc + bias + aux[row,col])

__device__ __forceinline__ float leaky_(float v) { return v > 0.0f ? v : 0.01f * v; }

__device__ __forceinline__ unsigned f2bf2(float lo, float hi) {
    __nv_bfloat162 h = __floats2bfloat162_rn(lo, hi);
    return *reinterpret_cast<unsigned*>(&h);
}

// bf16 m16n8k16 mma, fp32 accumulate
__device__ __forceinline__ void mma_bf16(float* d, const unsigned* a, const unsigned* b) {
    asm volatile(
        "mma.sync.aligned.m16n8k16.row.col.f32.bf16.bf16.f32 "
        "{%0,%1,%2,%3}, {%4,%5,%6,%7}, {%8,%9}, {%0,%1,%2,%3};"
        : "+f"(d[0]), "+f"(d[1]), "+f"(d[2]), "+f"(d[3])
        : "r"(a[0]), "r"(a[1]), "r"(a[2]), "r"(a[3]), "r"(b[0]), "r"(b[1]));
}

// ---------------------------------------------------------------------------
// Unified bf16 tensor-core GEMM: C[M,BN] = op(A[M,K]) @ B[BN,K]^T
// BK=32 (2 k16 MMA steps per tile), double-buffered, 256 threads.
// smem bf16 packed 2/word, row stride SW=20 words (conflict-free: the 8
// row-groups r*20 mod 32 cover all banks; frag LDS and 16B fills clean).
// All K here are multiples of 32 (1024/128/64).
// ---------------------------------------------------------------------------
template <int BN, int MODE, bool ABF16, bool OUTBF16, bool BBF16>
__global__ __launch_bounds__(256) void mma_gemm(
    const void* __restrict__ Av, const void* __restrict__ Bv,
    void* __restrict__ Cv, int M, int K,
    const float* __restrict__ bias, const float* __restrict__ aux)
{
    constexpr int BM = 128, BK = 32, SW = 20;
    constexpr int WARPS_M = (BN == 128) ? 2 : 4;
    constexpr int WM = BM / WARPS_M;
    constexpr int MT = WM / 16;
    constexpr int NT = 4;

    __shared__ unsigned sA[2][BM * SW];
    __shared__ unsigned sB[2][BN * SW];
    __shared__ float sNorm[(MODE == MODE_NORM) ? BM : 1];

    const int t    = threadIdx.x;
    const int wid  = t >> 5;
    const int lane = t & 31;
    const int gid  = lane >> 2;
    const int tidg = lane & 3;
    const int wm   = (wid % WARPS_M) * WM;
    const int wn   = (wid / WARPS_M) * 32;
    const int m0   = blockIdx.x * BM;

    uint4  aRegV[2];
    float4 aRegF[4];
    uint4  bRegV[2];
    float4 bRegF[4];

    float acc[MT][NT][4];
#pragma unroll
    for (int i = 0; i < MT; i++)
#pragma unroll
        for (int j = 0; j < NT; j++)
#pragma unroll
            for (int q = 0; q < 4; q++) acc[i][j][q] = 0.0f;

#define LOAD_A(K0)                                                            \
    if (ABF16) {                                                              \
        const __nv_bfloat16* Ab = (const __nv_bfloat16*)Av;                   \
        _Pragma("unroll")                                                     \
        for (int i = 0; i < 2; i++) {                                         \
            int fid = t + i * 256;                                            \
            int r = fid >> 2, c = fid & 3;                                    \
            int row = m0 + r;                                                 \
            aRegV[i] = make_uint4(0u, 0u, 0u, 0u);                            \
            if (row < M)                                                      \
                aRegV[i] = *(const uint4*)&Ab[(size_t)row * K + (K0) + c * 8];\
        }                                                                     \
    } else {                                                                  \
        const float* Af = (const float*)Av;                                   \
        _Pragma("unroll")                                                     \
        for (int i = 0; i < 4; i++) {                                         \
            int fid = t + i * 256;                                            \
            int r = fid >> 3, c = fid & 7;                                    \
            int row = m0 + r;                                                 \
            float4 v = make_float4(0.f, 0.f, 0.f, 0.f);                       \
            if (row < M) v = *(const float4*)&Af[(size_t)row*K + (K0) + c*4]; \
            aRegF[i] = v;                                                     \
        }                                                                     \
    }

#define STORE_A(BUF)                                                          \
    if (ABF16) {                                                              \
        _Pragma("unroll")                                                     \
        for (int i = 0; i < 2; i++) {                                         \
            int fid = t + i * 256;                                            \
            int r = fid >> 2, c = fid & 3;                                    \
            *(uint4*)&sA[BUF][r * SW + c * 4] = aRegV[i];                     \
        }                                                                     \
    } else {                                                                  \
        _Pragma("unroll")                                                     \
        for (int i = 0; i < 4; i++) {                                         \
            int fid = t + i * 256;                                            \
            int r = fid >> 3, c = fid & 7;                                    \
            float4 v = aRegF[i];                                              \
            if (MODE == MODE_G) {                                             \
                v.x = leaky_(v.x); v.y = leaky_(v.y);                         \
                v.z = leaky_(v.z); v.w = leaky_(v.w);                         \
            }                                                                 \
            uint2 u = make_uint2(f2bf2(v.x, v.y), f2bf2(v.z, v.w));           \
            *(uint2*)&sA[BUF][r * SW + c * 2] = u;                            \
        }                                                                     \
    }

#define LOAD_B(K0)                                                            \
    if (BBF16) {                                                              \
        const __nv_bfloat16* Bb = (const __nv_bfloat16*)Bv;                   \
        if (BN == 128) {                                                      \
            _Pragma("unroll")                                                 \
            for (int i = 0; i < 2; i++) {                                     \
                int fid = t + i * 256;                                        \
                int n = fid >> 2, c = fid & 3;                                \
                bRegV[i] = *(const uint4*)&Bb[(size_t)n * K + (K0) + c * 8];  \
            }                                                                 \
        } else {                                                              \
            int n = t >> 2, c = t & 3;                                        \
            bRegV[0] = *(const uint4*)&Bb[(size_t)n * K + (K0) + c * 8];      \
        }                                                                     \
    } else {                                                                  \
        const float* Bf = (const float*)Bv;                                   \
        if (BN == 128) {                                                      \
            _Pragma("unroll")                                                 \
            for (int i = 0; i < 4; i++) {                                     \
                int fid = t + i * 256;                                        \
                int n = fid >> 3, c = fid & 7;                                \
                bRegF[i] = *(const float4*)&Bf[(size_t)n * K + (K0) + c * 4]; \
            }                                                                 \
        } else {                                                              \
            _Pragma("unroll")                                                 \
            for (int i = 0; i < 2; i++) {                                     \
                int fid = t + i * 256;                                        \
                int n = fid >> 3, c = fid & 7;                                \
                bRegF[i] = *(const float4*)&Bf[(size_t)n * K + (K0) + c * 4]; \
            }                                                                 \
        }                                                                     \
    }

#define STORE_B(BUF)                                                          \
    if (BBF16) {                                                              \
        if (BN == 128) {                                                      \
            _Pragma("unroll")                                                 \
            for (int i = 0; i < 2; i++) {                                     \
                int fid = t + i * 256;                                        \
                int n = fid >> 2, c = fid & 3;                                \
                *(uint4*)&sB[BUF][n * SW + c * 4] = bRegV[i];                 \
            }                                                                 \
        } else {                                                              \
            int n = t >> 2, c = t & 3;                                        \
            *(uint4*)&sB[BUF][n * SW + c * 4] = bRegV[0];                     \
        }                                                                     \
    } else {                                                                  \
        constexpr int NB_IT = (BN == 128) ? 4 : 2;                            \
        _Pragma("unroll")                                                     \
        for (int i = 0; i < NB_IT; i++) {                                     \
            int fid = t + i * 256;                                            \
            int n = fid >> 3, c = fid & 7;                                    \
            float4 v = bRegF[i];                                              \
            uint2 u = make_uint2(f2bf2(v.x, v.y), f2bf2(v.z, v.w));           \
            *(uint2*)&sB[BUF][n * SW + c * 2] = u;                            \
        }                                                                     \
    }

    const int nk = K / BK;
    LOAD_A(0); LOAD_B(0);
    STORE_A(0); STORE_B(0);
    __syncthreads();

    for (int it = 0; it < nk; it++) {
        const int buf = it & 1;
        if (it + 1 < nk) { LOAD_A((it + 1) * BK); LOAD_B((it + 1) * BK); }

#pragma unroll
        for (int s = 0; s < 2; s++) {          // two k16 steps per BK=32 tile
            const int ko = s * 8;              // word offset within row
            unsigned af[MT][4];
#pragma unroll
            for (int mt = 0; mt < MT; mt++) {
                int base = (wm + mt * 16 + gid) * SW + ko;
                af[mt][0] = sA[buf][base + tidg];
                af[mt][1] = sA[buf][base + 8 * SW + tidg];
                af[mt][2] = sA[buf][base + tidg + 4];
                af[mt][3] = sA[buf][base + 8 * SW + tidg + 4];
            }
            unsigned bf[NT][2];
#pragma unroll
            for (int nt = 0; nt < NT; nt++) {
                int nb = (wn + nt * 8 + gid) * SW + ko;
                bf[nt][0] = sB[buf][nb + tidg];
                bf[nt][1] = sB[buf][nb + tidg + 4];
            }
#pragma unroll
            for (int mt = 0; mt < MT; mt++)
#pragma unroll
                for (int nt = 0; nt < NT; nt++)
                    mma_bf16(acc[mt][nt], af[mt], bf[nt]);
        }

        if (it + 1 < nk) {
            STORE_A(buf ^ 1); STORE_B(buf ^ 1);
            __syncthreads();
        }
    }

    // ---- epilogue ----
    if (MODE == MODE_NORM) {
        if (t < BM) sNorm[t] = 0.0f;
        __syncthreads();
#pragma unroll
        for (int mt = 0; mt < MT; mt++)
#pragma unroll
            for (int nt = 0; nt < NT; nt++) {
                int col = wn + nt * 8 + 2 * tidg;
#pragma unroll
                for (int half = 0; half < 2; half++) {
                    int rl = wm + mt * 16 + gid + half * 8;
                    if (m0 + rl >= M) continue;
                    float v0 = acc[mt][nt][half * 2 + 0] + bias[col];
                    float v1 = acc[mt][nt][half * 2 + 1] + bias[col + 1];
                    acc[mt][nt][half * 2 + 0] = v0;
                    acc[mt][nt][half * 2 + 1] = v1;
                    atomicAdd(&sNorm[rl], v0 * v0 + v1 * v1);
                }
            }
        __syncthreads();
        if (t < BM) sNorm[t] = 1.0f / fmaxf(sqrtf(sNorm[t]), 1e-12f);
        __syncthreads();
    }

#pragma unroll
    for (int mt = 0; mt < MT; mt++)
#pragma unroll
        for (int nt = 0; nt < NT; nt++) {
            int col = wn + nt * 8 + 2 * tidg;
#pragma unroll
            for (int half = 0; half < 2; half++) {
                int rl = wm + mt * 16 + gid + half * 8;
                int row = m0 + rl;
                if (row >= M) continue;
                float v0 = acc[mt][nt][half * 2 + 0];
                float v1 = acc[mt][nt][half * 2 + 1];
                if (MODE == MODE_NORM) {
                    float inv = sNorm[rl];
                    v0 *= inv; v1 *= inv;
                } else if (MODE == MODE_LIN) {
                    v0 = leaky_(v0 + bias[col]) + aux[(size_t)row * BN + col];
                    v1 = leaky_(v1 + bias[col + 1]) + aux[(size_t)row * BN + col + 1];
                } else if (MODE == MODE_G) {
                    v0 = leaky_(v0 + bias[col] + aux[(size_t)row * BN + col]);
                    v1 = leaky_(v1 + bias[col + 1] + aux[(size_t)row * BN + col + 1]);
                }
                if (OUTBF16) {
                    __nv_bfloat16* C = (__nv_bfloat16*)Cv;
                    *(__nv_bfloat162*)&C[(size_t)row * BN + col] =
                        __floats2bfloat162_rn(v0, v1);
                } else {
                    float* C = (float*)Cv;
                    *(float2*)&C[(size_t)row * BN + col] = make_float2(v0, v1);
                }
            }
        }
#undef LOAD_A
#undef STORE_A
#undef LOAD_B
#undef STORE_B
}

// ---------------------------------------------------------------------------
// Weight transpose + bf16 convert: src [Kdim][Ndim] fp32 -> dst [Ndim][Kdim] bf16
// ---------------------------------------------------------------------------
__global__ void transpose_cvt(const float* __restrict__ src,
                              __nv_bfloat16* __restrict__ dst, int Kdim, int Ndim)
{
    int i = blockIdx.x * 256 + threadIdx.x;
    if (i < Kdim * Ndim) {
        int k = i / Ndim, n = i % Ndim;
        dst[(size_t)n * Kdim + k] = __float2bfloat16(src[i]);
    }
}

// ---------------------------------------------------------------------------
// Fused copy + row-wise L2 normalize for preference rows; bf16 output
// ---------------------------------------------------------------------------
__global__ void pref_norm_kernel(const float* __restrict__ src,
                                 __nv_bfloat16* __restrict__ dst, int nrows)
{
    int warp = (blockIdx.x * blockDim.x + threadIdx.x) >> 5;
    int lane = threadIdx.x & 31;
    if (warp >= nrows) return;
    float4 v = *(const float4*)&src[(size_t)warp * 128 + lane * 4];
    float ss = v.x * v.x + v.y * v.y + v.z * v.z + v.w * v.w;
#pragma unroll
    for (int o = 16; o; o >>= 1) ss += __shfl_xor_sync(0xffffffffu, ss, o);
    float inv = 1.0f / fmaxf(sqrtf(ss), 1e-12f);
    uint2 u = make_uint2(f2bf2(v.x * inv, v.y * inv), f2bf2(v.z * inv, v.w * inv));
    *(uint2*)&dst[(size_t)warp * 128 + lane * 4] = u;
}

// ---------------------------------------------------------------------------
// CSR build: histogram of dst, 3-phase exclusive scan, src reorder by dst
// ---------------------------------------------------------------------------
__global__ void hist_kernel(const int* __restrict__ ei, int* __restrict__ cnt)
{
    int e = blockIdx.x * blockDim.x + threadIdx.x;
    if (e < NE_) atomicAdd(&cnt[__ldg(&ei[NE_ + e])], 1);
}

__global__ void scan1_kernel(const int* __restrict__ in, int* __restrict__ out,
                             int* __restrict__ part, int n)
{
    __shared__ int s[1024];
    int i = blockIdx.x * 1024 + threadIdx.x;
    int v = (i < n) ? in[i] : 0;
    s[threadIdx.x] = v;
    __syncthreads();
#pragma unroll
    for (int o = 1; o < 1024; o <<= 1) {
        int y = (threadIdx.x >= o) ? s[threadIdx.x - o] : 0;
        __syncthreads();
        s[threadIdx.x] += y;
        __syncthreads();
    }
    if (i < n) out[i] = s[threadIdx.x] - v;
    if (threadIdx.x == 1023) part[blockIdx.x] = s[1023];
}

__global__ void scan2_kernel(int* __restrict__ part, int nb)
{
    __shared__ int s[128];
    int v = (threadIdx.x < nb) ? part[threadIdx.x] : 0;
    s[threadIdx.x] = v;
    __syncthreads();
#pragma unroll
    for (int o = 1; o < 128; o <<= 1) {
        int y = (threadIdx.x >= o) ? s[threadIdx.x - o] : 0;
        __syncthreads();
        s[threadIdx.x] += y;
        __syncthreads();
    }
    if (threadIdx.x < nb) part[threadIdx.x] = s[threadIdx.x] - v;  // exclusive
}

__global__ void scan3_kernel(int* __restrict__ out, const int* __restrict__ part, int n)
{
    int i = blockIdx.x * 1024 + threadIdx.x;
    if (i < n) out[i] += part[blockIdx.x];
}

__global__ void reorder_kernel(const int* __restrict__ ei, int* __restrict__ pos,
                               int* __restrict__ srcs)
{
    int e = blockIdx.x * blockDim.x + threadIdx.x;
    if (e >= NE_) return;
    int d = __ldg(&ei[NE_ + e]);
    int idx = atomicAdd(&pos[d], 1);
    srcs[idx] = __ldg(&ei[e]);
}

// ---------------------------------------------------------------------------
// Atomic-free segmented scatter over bf16 xw (16B lanes):
//   h[d] = sum_{e: dst=d} float(xw[srcs[e]])   (fp32 out)
// ---------------------------------------------------------------------------
template <int D>
__global__ void seg_scatter(const __nv_bfloat16* __restrict__ xw,
                            const int* __restrict__ offs,
                            const int* __restrict__ srcs,
                            float* __restrict__ h)
{
    constexpr int G = D / 8;
    int gt   = blockIdx.x * blockDim.x + threadIdx.x;
    int node = gt / G;
    int q    = threadIdx.x % G;
    if (node >= NN_) return;

    int s   = __ldg(&offs[node]);
    int end = __ldg(&offs[node + 1]);

    float a[8] = {0,0,0,0,0,0,0,0};
    float b[8] = {0,0,0,0,0,0,0,0};

#define ACC8(dst, u)                                                        \
    {                                                                       \
        float2 f;                                                           \
        f = __bfloat1622float2(*(const __nv_bfloat162*)&(u).x);             \
        dst[0] += f.x; dst[1] += f.y;                                       \
        f = __bfloat1622float2(*(const __nv_bfloat162*)&(u).y);             \
        dst[2] += f.x; dst[3] += f.y;                                       \
        f = __bfloat1622float2(*(const __nv_bfloat162*)&(u).z);             \
        dst[4] += f.x; dst[5] += f.y;                                       \
        f = __bfloat1622float2(*(const __nv_bfloat162*)&(u).w);             \
        dst[6] += f.x; dst[7] += f.y;                                       \
    }

    int i = s;
    for (; i + 3 < end; i += 4) {
        int s0 = __ldg(&srcs[i + 0]);
        int s1 = __ldg(&srcs[i + 1]);
        int s2 = __ldg(&srcs[i + 2]);
        int s3 = __ldg(&srcs[i + 3]);
        uint4 u0 = *(const uint4*)&xw[(size_t)s0 * D + q * 8];
        uint4 u1 = *(const uint4*)&xw[(size_t)s1 * D + q * 8];
        uint4 u2 = *(const uint4*)&xw[(size_t)s2 * D + q * 8];
        uint4 u3 = *(const uint4*)&xw[(size_t)s3 * D + q * 8];
        ACC8(a, u0); ACC8(b, u1); ACC8(a, u2); ACC8(b, u3);
    }
    for (; i < end; i++) {
        int s0 = __ldg(&srcs[i]);
        uint4 u0 = *(const uint4*)&xw[(size_t)s0 * D + q * 8];
        ACC8(a, u0);
    }
#undef ACC8

    float4 r0 = make_float4(a[0] + b[0], a[1] + b[1], a[2] + b[2], a[3] + b[3]);
    float4 r1 = make_float4(a[4] + b[4], a[5] + b[5], a[6] + b[6], a[7] + b[7]);
    *(float4*)&h[(size_t)node * D + q * 8]     = r0;
    *(float4*)&h[(size_t)node * D + q * 8 + 4] = r1;
}

// ---------------------------------------------------------------------------
extern "C" void kernel_launch(void* const* d_in, const int* in_sizes, int n_in,
                              void* d_out, int out_size)
{
    const float* features = (const float*)d_in[0];
    const float* id_emb   = (const float*)d_in[1];
    const float* pref     = (const float*)d_in[2];
    const float* mlp_w    = (const float*)d_in[3];
    const float* mlp_b    = (const float*)d_in[4];
    const float* conv1_w  = (const float*)d_in[5];
    const float* lin1_w   = (const float*)d_in[6];
    const float* lin1_b   = (const float*)d_in[7];
    const float* g1_w     = (const float*)d_in[8];
    const float* g1_b     = (const float*)d_in[9];
    const float* conv2_w  = (const float*)d_in[10];
    const float* lin2_w   = (const float*)d_in[11];
    const float* lin2_b   = (const float*)d_in[12];
    const float* g2_w     = (const float*)d_in[13];
    const float* g2_b     = (const float*)d_in[14];
    const int*   ei       = (const int*)d_in[15];
    float* out = (float*)d_out;

    float *ph, *pxhat;
    __nv_bfloat16 *px, *pxw, *px2, *pwc1, *pwc2;
    int *pcnt, *poffs, *ppart, *ppos, *psrcs;
    cudaGetSymbolAddress((void**)&px,    g_x);
    cudaGetSymbolAddress((void**)&pxw,   g_xw);
    cudaGetSymbolAddress((void**)&ph,    g_h);
    cudaGetSymbolAddress((void**)&px2,   g_x2);
    cudaGetSymbolAddress((void**)&pxhat, g_xhat);
    cudaGetSymbolAddress((void**)&pwc1,  g_wc1);
    cudaGetSymbolAddress((void**)&pwc2,  g_wc2);
    cudaGetSymbolAddress((void**)&pcnt,  g_cnt);
    cudaGetSymbolAddress((void**)&poffs, g_offs);
    cudaGetSymbolAddress((void**)&ppart, g_part);
    cudaGetSymbolAddress((void**)&ppos,  g_pos);
    cudaGetSymbolAddress((void**)&psrcs, g_srcs);

    const int GB_N  = (NN_ + 127) / 128;
    const int NSCAN = NN_ + 1;
    const int NBLK  = (NSCAN + 1023) / 1024;

    static cudaStream_t s_side = nullptr;
    static cudaEvent_t ev_fork = nullptr, ev_join = nullptr, ev_mlp = nullptr,
                       ev_lin1 = nullptr, ev_g1 = nullptr, ev_lin2 = nullptr;
    if (!s_side) {
        cudaStreamCreateWithFlags(&s_side, cudaStreamNonBlocking);
        cudaEventCreateWithFlags(&ev_fork, cudaEventDisableTiming);
        cudaEventCreateWithFlags(&ev_join, cudaEventDisableTiming);
        cudaEventCreateWithFlags(&ev_mlp,  cudaEventDisableTiming);
        cudaEventCreateWithFlags(&ev_lin1, cudaEventDisableTiming);
        cudaEventCreateWithFlags(&ev_g1,   cudaEventDisableTiming);
        cudaEventCreateWithFlags(&ev_lin2, cudaEventDisableTiming);
    }

    // ---- fork: first 5 side-stream launches (so the MLP is launch #6 and
    //      gets captured by ncu's -s 5 -c 1) ----
    cudaEventRecord(ev_fork, 0);
    cudaStreamWaitEvent(s_side, ev_fork, 0);
    cudaMemsetAsync(pcnt, 0, NSCAN * sizeof(int), s_side);                    // 1
    hist_kernel<<<(NE_ + 255) / 256, 256, 0, s_side>>>(ei, pcnt);             // 2
    scan1_kernel<<<NBLK, 1024, 0, s_side>>>(pcnt, poffs, ppart, NSCAN);       // 3
    scan2_kernel<<<1, 128, 0, s_side>>>(ppart, NBLK);                         // 4
    scan3_kernel<<<NBLK, 1024, 0, s_side>>>(poffs, ppart, NSCAN);             // 5

    // ---- main: MLP (x[NU:] = normalize(features @ mlp_w^T + mlp_b))  -- #6
    mma_gemm<128, MODE_NORM, false, true, false><<<(NI_ + 127) / 128, 256>>>(
        features, mlp_w, px + (size_t)NU_ * DL_, NI_, DF_, mlp_b, nullptr);
    cudaEventRecord(ev_mlp, 0);

    // ---- remaining side-stream work ----
    cudaMemcpyAsync(ppos, poffs, NN_ * sizeof(int), cudaMemcpyDeviceToDevice, s_side);
    reorder_kernel<<<(NE_ + 255) / 256, 256, 0, s_side>>>(ei, ppos, psrcs);
    transpose_cvt<<<(DL_ * DL_ + 255) / 256, 256, 0, s_side>>>(conv1_w, pwc1, DL_, DL_);
    transpose_cvt<<<(DI_ * DI_ + 255) / 256, 256, 0, s_side>>>(conv2_w, pwc2, DI_, DI_);
    pref_norm_kernel<<<(NU_ * 32 + 255) / 256, 256, 0, s_side>>>(pref, px, NU_);
    cudaEventRecord(ev_join, s_side);

    // side: lin1 overlapped with conv1+scatter (waits MLP + in-order after pref)
    cudaStreamWaitEvent(s_side, ev_mlp, 0);
    mma_gemm<64, MODE_LIN, true, false, false><<<GB_N, 256, 0, s_side>>>(
        px, lin1_w, pxhat, NN_, DL_, lin1_b, id_emb);
    cudaEventRecord(ev_lin1, s_side);

    cudaStreamWaitEvent(0, ev_join, 0);

    // ===== layer 1 (main) =====
    mma_gemm<128, MODE_PLAIN, true, true, true><<<GB_N, 256>>>(
        px, pwc1, pxw, NN_, DL_, nullptr, nullptr);
    seg_scatter<128><<<(NN_ * 16 + 255) / 256, 256>>>(pxw, poffs, psrcs, ph);
    cudaStreamWaitEvent(0, ev_lin1, 0);
    mma_gemm<64, MODE_G, false, true, false><<<GB_N, 256>>>(
        ph, g1_w, px2, NN_, DL_, g1_b, pxhat);
    cudaEventRecord(ev_g1, 0);

    // side: lin2 overlapped with conv2+scatter64
    cudaStreamWaitEvent(s_side, ev_g1, 0);
    mma_gemm<64, MODE_LIN, true, false, false><<<GB_N, 256, 0, s_side>>>(
        px2, lin2_w, pxhat, NN_, DI_, lin2_b, id_emb);
    cudaEventRecord(ev_lin2, s_side);

    // ===== layer 2 (main) =====
    mma_gemm<64, MODE_PLAIN, true, true, true><<<GB_N, 256>>>(
        px2, pwc2, pxw, NN_, DI_, nullptr, nullptr);
    seg_scatter<64><<<(NN_ * 8 + 255) / 256, 256>>>(pxw, poffs, psrcs, ph);
    cudaStreamWaitEvent(0, ev_lin2, 0);
    mma_gemm<64, MODE_G, false, false, false><<<GB_N, 256>>>(
        ph, g2_w, out, NN_, DI_, g2_b, pxhat);
}

// round 14
// speedup vs baseline: 1.4715x; 1.0521x over previous
#include <cuda_runtime.h>
#include <cuda_bf16.h>
#include <math.h>

// Problem constants (fixed shapes per reference)
#define NU_  40000
#define NI_  60000
#define NN_  100000
#define DF_  1024
#define DL_  128
#define DI_  64
#define NE_  1600000

// Scratch buffers (device globals: allocation-guard safe)
__device__ __align__(16) __nv_bfloat16 g_x [(size_t)NN_ * DL_];  // x (bf16)
__device__ __align__(16) __nv_bfloat16 g_xw[(size_t)NN_ * DL_];  // conv out (bf16)
__device__ __align__(16) __nv_bfloat16 g_h [(size_t)NN_ * DL_];  // leaky(segsum) bf16
__device__ __align__(16) __nv_bfloat16 g_x2[(size_t)NN_ * DI_];  // layer-1 out (bf16)
__device__ float g_xhat[(size_t)NN_ * DI_];                      // lin output fp32
// bf16 transposed weight copies (built on side stream)
__device__ __align__(16) __nv_bfloat16 g_wc1[DL_ * DL_];  // conv1_w^T [n][k]
__device__ __align__(16) __nv_bfloat16 g_wc2[DI_ * DI_];  // conv2_w^T [n][k]
// CSR build scratch
__device__ int g_cnt [NN_ + 1];
__device__ int g_offs[NN_ + 1];
__device__ int g_part[128];
__device__ int g_pos [NN_];
__device__ int g_srcs[NE_];

#define MODE_NORM  0   // v = acc + bias; row L2 norm
#define MODE_PLAIN 1   // v = acc
#define MODE_LIN   2   // v = leaky(acc + bias) + aux[row,col]
#define MODE_G     3   // v = leaky(acc + bias + aux[row,col]); A = pre-leaky'd bf16

__device__ __forceinline__ float leaky_(float v) { return v > 0.0f ? v : 0.01f * v; }

__device__ __forceinline__ unsigned f2bf2(float lo, float hi) {
    __nv_bfloat162 h = __floats2bfloat162_rn(lo, hi);
    return *reinterpret_cast<unsigned*>(&h);
}

// bf16 m16n8k16 mma, fp32 accumulate
__device__ __forceinline__ void mma_bf16(float* d, const unsigned* a, const unsigned* b) {
    asm volatile(
        "mma.sync.aligned.m16n8k16.row.col.f32.bf16.bf16.f32 "
        "{%0,%1,%2,%3}, {%4,%5,%6,%7}, {%8,%9}, {%0,%1,%2,%3};"
        : "+f"(d[0]), "+f"(d[1]), "+f"(d[2]), "+f"(d[3])
        : "r"(a[0]), "r"(a[1]), "r"(a[2]), "r"(a[3]), "r"(b[0]), "r"(b[1]));
}

__device__ __forceinline__ void ldsm_x4(unsigned* r, unsigned addr) {
    asm volatile("ldmatrix.sync.aligned.m8n8.x4.shared.b16 {%0,%1,%2,%3}, [%4];"
                 : "=r"(r[0]), "=r"(r[1]), "=r"(r[2]), "=r"(r[3]) : "r"(addr));
}

// ---------------------------------------------------------------------------
// Unified bf16 tensor-core GEMM: C[M,BN] = A[M,K] @ B[BN,K]^T
// BK=32 (2 k16 MMA steps per tile), double-buffered, 256 threads.
// smem bf16 packed 2/word, row stride SW=20 words; fragment loads use
// ldmatrix.x4 (SW=20 is conflict-free: row phases j*20 mod 32 hit all banks).
// ---------------------------------------------------------------------------
template <int BN, int MODE, bool ABF16, bool OUTBF16, bool BBF16>
__global__ __launch_bounds__(256) void mma_gemm(
    const void* __restrict__ Av, const void* __restrict__ Bv,
    void* __restrict__ Cv, int M, int K,
    const float* __restrict__ bias, const float* __restrict__ aux)
{
    constexpr int BM = 128, BK = 32, SW = 20;
    constexpr int WARPS_M = (BN == 128) ? 2 : 4;
    constexpr int WM = BM / WARPS_M;
    constexpr int MT = WM / 16;
    constexpr int NT = 4;

    __shared__ unsigned sA[2][BM * SW];
    __shared__ unsigned sB[2][BN * SW];
    __shared__ float sNorm[(MODE == MODE_NORM) ? BM : 1];

    const int t    = threadIdx.x;
    const int wid  = t >> 5;
    const int lane = t & 31;
    const int gid  = lane >> 2;
    const int tidg = lane & 3;
    const int wm   = (wid % WARPS_M) * WM;
    const int wn   = (wid / WARPS_M) * 32;
    const int m0   = blockIdx.x * BM;

    const unsigned sA_u = (unsigned)__cvta_generic_to_shared(&sA[0][0]);
    const unsigned sB_u = (unsigned)__cvta_generic_to_shared(&sB[0][0]);

    // ldmatrix per-lane word offsets
    // A (x4 = m16 x k16): lanes 0-7 rows 0-7 kh0, 8-15 rows 8-15 kh0,
    //                     16-23 rows 0-7 kh1, 24-31 rows 8-15 kh1
    const int a_row = (lane & 7) + ((lane >> 3) & 1) * 8;
    const int a_kw  = (lane >> 4) * 4;
    const int aw_off = a_row * SW + a_kw;
    // B (x4 = two n8 x k16): lanes 0-7 n-pair row grp 0 kh0, 8-15 grp0 kh1,
    //                        16-23 grp1 kh0, 24-31 grp1 kh1
    const int b_row = (lane & 7) + (lane >> 4) * 8;
    const int b_kw  = ((lane >> 3) & 1) * 4;
    const int bw_off = b_row * SW + b_kw;

    uint4  aRegV[2];
    float4 aRegF[4];
    uint4  bRegV[2];
    float4 bRegF[4];

    float acc[MT][NT][4];
#pragma unroll
    for (int i = 0; i < MT; i++)
#pragma unroll
        for (int j = 0; j < NT; j++)
#pragma unroll
            for (int q = 0; q < 4; q++) acc[i][j][q] = 0.0f;

#define LOAD_A(K0)                                                            \
    if (ABF16) {                                                              \
        const __nv_bfloat16* Ab = (const __nv_bfloat16*)Av;                   \
        _Pragma("unroll")                                                     \
        for (int i = 0; i < 2; i++) {                                         \
            int fid = t + i * 256;                                            \
            int r = fid >> 2, c = fid & 3;                                    \
            int row = m0 + r;                                                 \
            aRegV[i] = make_uint4(0u, 0u, 0u, 0u);                            \
            if (row < M)                                                      \
                aRegV[i] = *(const uint4*)&Ab[(size_t)row * K + (K0) + c * 8];\
        }                                                                     \
    } else {                                                                  \
        const float* Af = (const float*)Av;                                   \
        _Pragma("unroll")                                                     \
        for (int i = 0; i < 4; i++) {                                         \
            int fid = t + i * 256;                                            \
            int r = fid >> 3, c = fid & 7;                                    \
            int row = m0 + r;                                                 \
            float4 v = make_float4(0.f, 0.f, 0.f, 0.f);                       \
            if (row < M) v = *(const float4*)&Af[(size_t)row*K + (K0) + c*4]; \
            aRegF[i] = v;                                                     \
        }                                                                     \
    }

#define STORE_A(BUF)                                                          \
    if (ABF16) {                                                              \
        _Pragma("unroll")                                                     \
        for (int i = 0; i < 2; i++) {                                         \
            int fid = t + i * 256;                                            \
            int r = fid >> 2, c = fid & 3;                                    \
            *(uint4*)&sA[BUF][r * SW + c * 4] = aRegV[i];                     \
        }                                                                     \
    } else {                                                                  \
        _Pragma("unroll")                                                     \
        for (int i = 0; i < 4; i++) {                                         \
            int fid = t + i * 256;                                            \
            int r = fid >> 3, c = fid & 7;                                    \
            float4 v = aRegF[i];                                              \
            uint2 u = make_uint2(f2bf2(v.x, v.y), f2bf2(v.z, v.w));           \
            *(uint2*)&sA[BUF][r * SW + c * 2] = u;                            \
        }                                                                     \
    }

#define LOAD_B(K0)                                                            \
    if (BBF16) {                                                              \
        const __nv_bfloat16* Bb = (const __nv_bfloat16*)Bv;                   \
        if (BN == 128) {                                                      \
            _Pragma("unroll")                                                 \
            for (int i = 0; i < 2; i++) {                                     \
                int fid = t + i * 256;                                        \
                int n = fid >> 2, c = fid & 3;                                \
                bRegV[i] = *(const uint4*)&Bb[(size_t)n * K + (K0) + c * 8];  \
            }                                                                 \
        } else {                                                              \
            int n = t >> 2, c = t & 3;                                        \
            bRegV[0] = *(const uint4*)&Bb[(size_t)n * K + (K0) + c * 8];      \
        }                                                                     \
    } else {                                                                  \
        const float* Bf = (const float*)Bv;                                   \
        constexpr int NB_IT = (BN == 128) ? 4 : 2;                            \
        _Pragma("unroll")                                                     \
        for (int i = 0; i < NB_IT; i++) {                                     \
            int fid = t + i * 256;                                            \
            int n = fid >> 3, c = fid & 7;                                    \
            bRegF[i] = *(const float4*)&Bf[(size_t)n * K + (K0) + c * 4];     \
        }                                                                     \
    }

#define STORE_B(BUF)                                                          \
    if (BBF16) {                                                              \
        if (BN == 128) {                                                      \
            _Pragma("unroll")                                                 \
            for (int i = 0; i < 2; i++) {                                     \
                int fid = t + i * 256;                                        \
                int n = fid >> 2, c = fid & 3;                                \
                *(uint4*)&sB[BUF][n * SW + c * 4] = bRegV[i];                 \
            }                                                                 \
        } else {                                                              \
            int n = t >> 2, c = t & 3;                                        \
            *(uint4*)&sB[BUF][n * SW + c * 4] = bRegV[0];                     \
        }                                                                     \
    } else {                                                                  \
        constexpr int NB_IT = (BN == 128) ? 4 : 2;                            \
        _Pragma("unroll")                                                     \
        for (int i = 0; i < NB_IT; i++) {                                     \
            int fid = t + i * 256;                                            \
            int n = fid >> 3, c = fid & 7;                                    \
            float4 v = bRegF[i];                                              \
            uint2 u = make_uint2(f2bf2(v.x, v.y), f2bf2(v.z, v.w));           \
            *(uint2*)&sB[BUF][n * SW + c * 2] = u;                            \
        }                                                                     \
    }

    const int nk = K / BK;
    LOAD_A(0); LOAD_B(0);
    STORE_A(0); STORE_B(0);
    __syncthreads();

    for (int it = 0; it < nk; it++) {
        const int buf = it & 1;
        if (it + 1 < nk) { LOAD_A((it + 1) * BK); LOAD_B((it + 1) * BK); }

        const unsigned aBufU = sA_u + (unsigned)(buf * BM * SW) * 4u;
        const unsigned bBufU = sB_u + (unsigned)(buf * BN * SW) * 4u;

#pragma unroll
        for (int s = 0; s < 2; s++) {          // two k16 steps per BK=32 tile
            unsigned af[MT][4];
#pragma unroll
            for (int mt = 0; mt < MT; mt++)
                ldsm_x4(af[mt], aBufU +
                        (unsigned)((wm + mt * 16) * SW + s * 8 + aw_off) * 4u);
            unsigned bf[2][4];
#pragma unroll
            for (int p = 0; p < 2; p++)
                ldsm_x4(bf[p], bBufU +
                        (unsigned)((wn + p * 16) * SW + s * 8 + bw_off) * 4u);
#pragma unroll
            for (int mt = 0; mt < MT; mt++)
#pragma unroll
                for (int nt = 0; nt < NT; nt++)
                    mma_bf16(acc[mt][nt], af[mt], &bf[nt >> 1][(nt & 1) * 2]);
        }

        if (it + 1 < nk) {
            STORE_A(buf ^ 1); STORE_B(buf ^ 1);
            __syncthreads();
        }
    }

    // ---- epilogue ----
    if (MODE == MODE_NORM) {
        if (t < BM) sNorm[t] = 0.0f;
        __syncthreads();
#pragma unroll
        for (int mt = 0; mt < MT; mt++)
#pragma unroll
            for (int nt = 0; nt < NT; nt++) {
                int col = wn + nt * 8 + 2 * tidg;
#pragma unroll
                for (int half = 0; half < 2; half++) {
                    int rl = wm + mt * 16 + gid + half * 8;
                    if (m0 + rl >= M) continue;
                    float v0 = acc[mt][nt][half * 2 + 0] + bias[col];
                    float v1 = acc[mt][nt][half * 2 + 1] + bias[col + 1];
                    acc[mt][nt][half * 2 + 0] = v0;
                    acc[mt][nt][half * 2 + 1] = v1;
                    atomicAdd(&sNorm[rl], v0 * v0 + v1 * v1);
                }
            }
        __syncthreads();
        if (t < BM) sNorm[t] = 1.0f / fmaxf(sqrtf(sNorm[t]), 1e-12f);
        __syncthreads();
    }

#pragma unroll
    for (int mt = 0; mt < MT; mt++)
#pragma unroll
        for (int nt = 0; nt < NT; nt++) {
            int col = wn + nt * 8 + 2 * tidg;
#pragma unroll
            for (int half = 0; half < 2; half++) {
                int rl = wm + mt * 16 + gid + half * 8;
                int row = m0 + rl;
                if (row >= M) continue;
                float v0 = acc[mt][nt][half * 2 + 0];
                float v1 = acc[mt][nt][half * 2 + 1];
                if (MODE == MODE_NORM) {
                    float inv = sNorm[rl];
                    v0 *= inv; v1 *= inv;
                } else if (MODE == MODE_LIN) {
                    v0 = leaky_(v0 + bias[col]) + aux[(size_t)row * BN + col];
                    v1 = leaky_(v1 + bias[col + 1]) + aux[(size_t)row * BN + col + 1];
                } else if (MODE == MODE_G) {
                    v0 = leaky_(v0 + bias[col] + aux[(size_t)row * BN + col]);
                    v1 = leaky_(v1 + bias[col + 1] + aux[(size_t)row * BN + col + 1]);
                }
                if (OUTBF16) {
                    __nv_bfloat16* C = (__nv_bfloat16*)Cv;
                    *(__nv_bfloat162*)&C[(size_t)row * BN + col] =
                        __floats2bfloat162_rn(v0, v1);
                } else {
                    float* C = (float*)Cv;
                    *(float2*)&C[(size_t)row * BN + col] = make_float2(v0, v1);
                }
            }
        }
#undef LOAD_A
#undef STORE_A
#undef LOAD_B
#undef STORE_B
}

// ---------------------------------------------------------------------------
// Weight transpose + bf16 convert: src [Kdim][Ndim] fp32 -> dst [Ndim][Kdim] bf16
// ---------------------------------------------------------------------------
__global__ void transpose_cvt(const float* __restrict__ src,
                              __nv_bfloat16* __restrict__ dst, int Kdim, int Ndim)
{
    int i = blockIdx.x * 256 + threadIdx.x;
    if (i < Kdim * Ndim) {
        int k = i / Ndim, n = i % Ndim;
        dst[(size_t)n * Kdim + k] = __float2bfloat16(src[i]);
    }
}

// ---------------------------------------------------------------------------
// Fused copy + row-wise L2 normalize for preference rows; bf16 output
// ---------------------------------------------------------------------------
__global__ void pref_norm_kernel(const float* __restrict__ src,
                                 __nv_bfloat16* __restrict__ dst, int nrows)
{
    int warp = (blockIdx.x * blockDim.x + threadIdx.x) >> 5;
    int lane = threadIdx.x & 31;
    if (warp >= nrows) return;
    float4 v = *(const float4*)&src[(size_t)warp * 128 + lane * 4];
    float ss = v.x * v.x + v.y * v.y + v.z * v.z + v.w * v.w;
#pragma unroll
    for (int o = 16; o; o >>= 1) ss += __shfl_xor_sync(0xffffffffu, ss, o);
    float inv = 1.0f / fmaxf(sqrtf(ss), 1e-12f);
    uint2 u = make_uint2(f2bf2(v.x * inv, v.y * inv), f2bf2(v.z * inv, v.w * inv));
    *(uint2*)&dst[(size_t)warp * 128 + lane * 4] = u;
}

// ---------------------------------------------------------------------------
// CSR build: histogram of dst, 3-phase exclusive scan, src reorder by dst
// ---------------------------------------------------------------------------
__global__ void hist_kernel(const int* __restrict__ ei, int* __restrict__ cnt)
{
    int e = blockIdx.x * blockDim.x + threadIdx.x;
    if (e < NE_) atomicAdd(&cnt[__ldg(&ei[NE_ + e])], 1);
}

__global__ void scan1_kernel(const int* __restrict__ in, int* __restrict__ out,
                             int* __restrict__ part, int n)
{
    __shared__ int s[1024];
    int i = blockIdx.x * 1024 + threadIdx.x;
    int v = (i < n) ? in[i] : 0;
    s[threadIdx.x] = v;
    __syncthreads();
#pragma unroll
    for (int o = 1; o < 1024; o <<= 1) {
        int y = (threadIdx.x >= o) ? s[threadIdx.x - o] : 0;
        __syncthreads();
        s[threadIdx.x] += y;
        __syncthreads();
    }
    if (i < n) out[i] = s[threadIdx.x] - v;
    if (threadIdx.x == 1023) part[blockIdx.x] = s[1023];
}

__global__ void scan2_kernel(int* __restrict__ part, int nb)
{
    __shared__ int s[128];
    int v = (threadIdx.x < nb) ? part[threadIdx.x] : 0;
    s[threadIdx.x] = v;
    __syncthreads();
#pragma unroll
    for (int o = 1; o < 128; o <<= 1) {
        int y = (threadIdx.x >= o) ? s[threadIdx.x - o] : 0;
        __syncthreads();
        s[threadIdx.x] += y;
        __syncthreads();
    }
    if (threadIdx.x < nb) part[threadIdx.x] = s[threadIdx.x] - v;  // exclusive
}

__global__ void scan3_kernel(int* __restrict__ out, const int* __restrict__ part, int n)
{
    int i = blockIdx.x * 1024 + threadIdx.x;
    if (i < n) out[i] += part[blockIdx.x];
}

__global__ void reorder_kernel(const int* __restrict__ ei, int* __restrict__ pos,
                               int* __restrict__ srcs)
{
    int e = blockIdx.x * blockDim.x + threadIdx.x;
    if (e >= NE_) return;
    int d = __ldg(&ei[NE_ + e]);
    int idx = atomicAdd(&pos[d], 1);
    srcs[idx] = __ldg(&ei[e]);
}

// ---------------------------------------------------------------------------
// Atomic-free segmented scatter over bf16 xw (16B lanes); fp32 accumulate;
// output = leaky(sum) as bf16 (bit-identical to leaky-at-GEMM-fill).
// ---------------------------------------------------------------------------
template <int D>
__global__ void seg_scatter(const __nv_bfloat16* __restrict__ xw,
                            const int* __restrict__ offs,
                            const int* __restrict__ srcs,
                            __nv_bfloat16* __restrict__ h)
{
    constexpr int G = D / 8;
    int gt   = blockIdx.x * blockDim.x + threadIdx.x;
    int node = gt / G;
    int q    = threadIdx.x % G;
    if (node >= NN_) return;

    int s   = __ldg(&offs[node]);
    int end = __ldg(&offs[node + 1]);

    float a[8] = {0,0,0,0,0,0,0,0};
    float b[8] = {0,0,0,0,0,0,0,0};

#define ACC8(dst, u)                                                        \
    {                                                                       \
        float2 f;                                                           \
        f = __bfloat1622float2(*(const __nv_bfloat162*)&(u).x);             \
        dst[0] += f.x; dst[1] += f.y;                                       \
        f = __bfloat1622float2(*(const __nv_bfloat162*)&(u).y);             \
        dst[2] += f.x; dst[3] += f.y;                                       \
        f = __bfloat1622float2(*(const __nv_bfloat162*)&(u).z);             \
        dst[4] += f.x; dst[5] += f.y;                                       \
        f = __bfloat1622float2(*(const __nv_bfloat162*)&(u).w);             \
        dst[6] += f.x; dst[7] += f.y;                                       \
    }

    int i = s;
    for (; i + 3 < end; i += 4) {
        int s0 = __ldg(&srcs[i + 0]);
        int s1 = __ldg(&srcs[i + 1]);
        int s2 = __ldg(&srcs[i + 2]);
        int s3 = __ldg(&srcs[i + 3]);
        uint4 u0 = *(const uint4*)&xw[(size_t)s0 * D + q * 8];
        uint4 u1 = *(const uint4*)&xw[(size_t)s1 * D + q * 8];
        uint4 u2 = *(const uint4*)&xw[(size_t)s2 * D + q * 8];
        uint4 u3 = *(const uint4*)&xw[(size_t)s3 * D + q * 8];
        ACC8(a, u0); ACC8(b, u1); ACC8(a, u2); ACC8(b, u3);
    }
    for (; i < end; i++) {
        int s0 = __ldg(&srcs[i]);
        uint4 u0 = *(const uint4*)&xw[(size_t)s0 * D + q * 8];
        ACC8(a, u0);
    }
#undef ACC8

    uint4 r;
    r.x = f2bf2(leaky_(a[0] + b[0]), leaky_(a[1] + b[1]));
    r.y = f2bf2(leaky_(a[2] + b[2]), leaky_(a[3] + b[3]));
    r.z = f2bf2(leaky_(a[4] + b[4]), leaky_(a[5] + b[5]));
    r.w = f2bf2(leaky_(a[6] + b[6]), leaky_(a[7] + b[7]));
    *(uint4*)&h[(size_t)node * D + q * 8] = r;
}

// ---------------------------------------------------------------------------
extern "C" void kernel_launch(void* const* d_in, const int* in_sizes, int n_in,
                              void* d_out, int out_size)
{
    const float* features = (const float*)d_in[0];
    const float* id_emb   = (const float*)d_in[1];
    const float* pref     = (const float*)d_in[2];
    const float* mlp_w    = (const float*)d_in[3];
    const float* mlp_b    = (const float*)d_in[4];
    const float* conv1_w  = (const float*)d_in[5];
    const float* lin1_w   = (const float*)d_in[6];
    const float* lin1_b   = (const float*)d_in[7];
    const float* g1_w     = (const float*)d_in[8];
    const float* g1_b     = (const float*)d_in[9];
    const float* conv2_w  = (const float*)d_in[10];
    const float* lin2_w   = (const float*)d_in[11];
    const float* lin2_b   = (const float*)d_in[12];
    const float* g2_w     = (const float*)d_in[13];
    const float* g2_b     = (const float*)d_in[14];
    const int*   ei       = (const int*)d_in[15];
    float* out = (float*)d_out;

    float *pxhat;
    __nv_bfloat16 *px, *pxw, *ph, *px2, *pwc1, *pwc2;
    int *pcnt, *poffs, *ppart, *ppos, *psrcs;
    cudaGetSymbolAddress((void**)&px,    g_x);
    cudaGetSymbolAddress((void**)&pxw,   g_xw);
    cudaGetSymbolAddress((void**)&ph,    g_h);
    cudaGetSymbolAddress((void**)&px2,   g_x2);
    cudaGetSymbolAddress((void**)&pxhat, g_xhat);
    cudaGetSymbolAddress((void**)&pwc1,  g_wc1);
    cudaGetSymbolAddress((void**)&pwc2,  g_wc2);
    cudaGetSymbolAddress((void**)&pcnt,  g_cnt);
    cudaGetSymbolAddress((void**)&poffs, g_offs);
    cudaGetSymbolAddress((void**)&ppart, g_part);
    cudaGetSymbolAddress((void**)&ppos,  g_pos);
    cudaGetSymbolAddress((void**)&psrcs, g_srcs);

    const int GB_N  = (NN_ + 127) / 128;
    const int NSCAN = NN_ + 1;
    const int NBLK  = (NSCAN + 1023) / 1024;

    static cudaStream_t s_side = nullptr;
    static cudaEvent_t ev_fork = nullptr, ev_join = nullptr, ev_mlp = nullptr,
                       ev_lin1 = nullptr, ev_g1 = nullptr, ev_lin2 = nullptr;
    if (!s_side) {
        cudaStreamCreateWithFlags(&s_side, cudaStreamNonBlocking);
        cudaEventCreateWithFlags(&ev_fork, cudaEventDisableTiming);
        cudaEventCreateWithFlags(&ev_join, cudaEventDisableTiming);
        cudaEventCreateWithFlags(&ev_mlp,  cudaEventDisableTiming);
        cudaEventCreateWithFlags(&ev_lin1, cudaEventDisableTiming);
        cudaEventCreateWithFlags(&ev_g1,   cudaEventDisableTiming);
        cudaEventCreateWithFlags(&ev_lin2, cudaEventDisableTiming);
    }

    // ---- fork: CSR build + weight prep + pref_norm on side stream ----
    cudaEventRecord(ev_fork, 0);
    cudaStreamWaitEvent(s_side, ev_fork, 0);
    cudaMemsetAsync(pcnt, 0, NSCAN * sizeof(int), s_side);
    hist_kernel<<<(NE_ + 255) / 256, 256, 0, s_side>>>(ei, pcnt);
    scan1_kernel<<<NBLK, 1024, 0, s_side>>>(pcnt, poffs, ppart, NSCAN);
    scan2_kernel<<<1, 128, 0, s_side>>>(ppart, NBLK);
    scan3_kernel<<<NBLK, 1024, 0, s_side>>>(poffs, ppart, NSCAN);

    // ---- main: MLP (x[NU:] = normalize(features @ mlp_w^T + mlp_b))
    mma_gemm<128, MODE_NORM, false, true, false><<<(NI_ + 127) / 128, 256>>>(
        features, mlp_w, px + (size_t)NU_ * DL_, NI_, DF_, mlp_b, nullptr);
    cudaEventRecord(ev_mlp, 0);

    // ---- remaining side-stream work ----
    cudaMemcpyAsync(ppos, poffs, NN_ * sizeof(int), cudaMemcpyDeviceToDevice, s_side);
    reorder_kernel<<<(NE_ + 255) / 256, 256, 0, s_side>>>(ei, ppos, psrcs);
    transpose_cvt<<<(DL_ * DL_ + 255) / 256, 256, 0, s_side>>>(conv1_w, pwc1, DL_, DL_);
    transpose_cvt<<<(DI_ * DI_ + 255) / 256, 256, 0, s_side>>>(conv2_w, pwc2, DI_, DI_);
    pref_norm_kernel<<<(NU_ * 32 + 255) / 256, 256, 0, s_side>>>(pref, px, NU_);
    cudaEventRecord(ev_join, s_side);

    // side: lin1 overlapped with conv1+scatter (waits MLP)
    cudaStreamWaitEvent(s_side, ev_mlp, 0);
    mma_gemm<64, MODE_LIN, true, false, false><<<GB_N, 256, 0, s_side>>>(
        px, lin1_w, pxhat, NN_, DL_, lin1_b, id_emb);
    cudaEventRecord(ev_lin1, s_side);

    cudaStreamWaitEvent(0, ev_join, 0);

    // ===== layer 1 (main) =====
    mma_gemm<128, MODE_PLAIN, true, true, true><<<GB_N, 256>>>(
        px, pwc1, pxw, NN_, DL_, nullptr, nullptr);
    seg_scatter<128><<<(NN_ * 16 + 255) / 256, 256>>>(pxw, poffs, psrcs, ph);
    cudaStreamWaitEvent(0, ev_lin1, 0);
    mma_gemm<64, MODE_G, true, true, false><<<GB_N, 256>>>(
        ph, g1_w, px2, NN_, DL_, g1_b, pxhat);
    cudaEventRecord(ev_g1, 0);

    // side: lin2 overlapped with conv2+scatter64
    cudaStreamWaitEvent(s_side, ev_g1, 0);
    mma_gemm<64, MODE_LIN, true, false, false><<<GB_N, 256, 0, s_side>>>(
        px2, lin2_w, pxhat, NN_, DI_, lin2_b, id_emb);
    cudaEventRecord(ev_lin2, s_side);

    // ===== layer 2 (main) =====
    mma_gemm<64, MODE_PLAIN, true, true, true><<<GB_N, 256>>>(
        px2, pwc2, pxw, NN_, DI_, nullptr, nullptr);
    seg_scatter<64><<<(NN_ * 8 + 255) / 256, 256>>>(pxw, poffs, psrcs, ph);
    cudaStreamWaitEvent(0, ev_lin2, 0);
    mma_gemm<64, MODE_G, true, false, false><<<GB_N, 256>>>(
        ph, g2_w, out, NN_, DI_, g2_b, pxhat);
}

// round 16
// speedup vs baseline: 1.4733x; 1.0012x over previous
#include <cuda_runtime.h>
#include <cuda_bf16.h>
#include <math.h>

// Problem constants (fixed shapes per reference)
#define NU_  40000
#define NI_  60000
#define NN_  100000
#define DF_  1024
#define DL_  128
#define DI_  64
#define NE_  1600000

// Scratch buffers (device globals: allocation-guard safe)
__device__ __align__(16) __nv_bfloat16 g_x [(size_t)NN_ * DL_];  // x (bf16)
__device__ __align__(16) __nv_bfloat16 g_xw[(size_t)NN_ * DL_];  // conv out (bf16)
__device__ __align__(16) __nv_bfloat16 g_h [(size_t)NN_ * DL_];  // leaky(segsum) bf16
__device__ __align__(16) __nv_bfloat16 g_x2[(size_t)NN_ * DI_];  // layer-1 out (bf16)
__device__ float g_xhat[(size_t)NN_ * DI_];                      // lin output fp32
// bf16 weight copies (built on side stream)
__device__ __align__(16) __nv_bfloat16 g_wmlp [DL_ * DF_];  // mlp_w   [n=128][k=1024]
__device__ __align__(16) __nv_bfloat16 g_wc1  [DL_ * DL_];  // conv1_w^T [n=128][k=128]
__device__ __align__(16) __nv_bfloat16 g_wc2  [DI_ * DI_];  // conv2_w^T [n=64][k=64]
__device__ __align__(16) __nv_bfloat16 g_wlin1[DI_ * DL_];  // lin1_w  [n=64][k=128]
__device__ __align__(16) __nv_bfloat16 g_wg1  [DI_ * DL_];  // g1_w    [n=64][k=128]  (FIXED size)
__device__ __align__(16) __nv_bfloat16 g_wlin2[DI_ * DI_];  // lin2_w  [n=64][k=64]
__device__ __align__(16) __nv_bfloat16 g_wg2  [DI_ * DI_];  // g2_w    [n=64][k=64]
// CSR build scratch
__device__ int g_cnt [NN_ + 1];
__device__ int g_offs[NN_ + 1];
__device__ int g_part[128];
__device__ int g_pos [NN_];
__device__ int g_srcs[NE_];

#define MODE_NORM  0   // v = acc + bias; row L2 norm
#define MODE_PLAIN 1   // v = acc
#define MODE_LIN   2   // v = leaky(acc + bias) + aux[row,col]
#define MODE_G     3   // v = leaky(acc + bias + aux[row,col]); A = pre-leaky'd bf16

__device__ __forceinline__ float leaky_(float v) { return v > 0.0f ? v : 0.01f * v; }

__device__ __forceinline__ unsigned f2bf2(float lo, float hi) {
    __nv_bfloat162 h = __floats2bfloat162_rn(lo, hi);
    return *reinterpret_cast<unsigned*>(&h);
}

// bf16 m16n8k16 mma, fp32 accumulate
__device__ __forceinline__ void mma_bf16(float* d, const unsigned* a, const unsigned* b) {
    asm volatile(
        "mma.sync.aligned.m16n8k16.row.col.f32.bf16.bf16.f32 "
        "{%0,%1,%2,%3}, {%4,%5,%6,%7}, {%8,%9}, {%0,%1,%2,%3};"
        : "+f"(d[0]), "+f"(d[1]), "+f"(d[2]), "+f"(d[3])
        : "r"(a[0]), "r"(a[1]), "r"(a[2]), "r"(a[3]), "r"(b[0]), "r"(b[1]));
}

__device__ __forceinline__ void ldsm_x4(unsigned* r, unsigned addr) {
    asm volatile("ldmatrix.sync.aligned.m8n8.x4.shared.b16 {%0,%1,%2,%3}, [%4];"
                 : "=r"(r[0]), "=r"(r[1]), "=r"(r[2]), "=r"(r[3]) : "r"(addr));
}

// ---------------------------------------------------------------------------
// Unified bf16 tensor-core GEMM: C[M,BN] = A[M,K] @ B[BN,K]^T
// BK=32 (2 k16 MMA steps per tile), double-buffered, 256 threads.
// B is always bf16 [n][k] (pre-converted). A bf16 unless ABF16=false (fp32,
// cvt at fill). Fragment loads via ldmatrix.x4 on SW=20-word rows
// (conflict-free: row phases j*20 mod 32 hit all banks).
// ---------------------------------------------------------------------------
template <int BN, int MODE, bool ABF16, bool OUTBF16>
__global__ __launch_bounds__(256) void mma_gemm(
    const void* __restrict__ Av, const __nv_bfloat16* __restrict__ B,
    void* __restrict__ Cv, int M, int K,
    const float* __restrict__ bias, const float* __restrict__ aux)
{
    constexpr int BM = 128, BK = 32, SW = 20;
    constexpr int WARPS_M = (BN == 128) ? 2 : 4;
    constexpr int WM = BM / WARPS_M;
    constexpr int MT = WM / 16;
    constexpr int NT = 4;

    __shared__ unsigned sA[2][BM * SW];
    __shared__ unsigned sB[2][BN * SW];
    __shared__ float sNorm[(MODE == MODE_NORM) ? BM : 1];

    const int t    = threadIdx.x;
    const int wid  = t >> 5;
    const int lane = t & 31;
    const int gid  = lane >> 2;
    const int tidg = lane & 3;
    const int wm   = (wid % WARPS_M) * WM;
    const int wn   = (wid / WARPS_M) * 32;
    const int m0   = blockIdx.x * BM;

    const unsigned sA_u = (unsigned)__cvta_generic_to_shared(&sA[0][0]);
    const unsigned sB_u = (unsigned)__cvta_generic_to_shared(&sB[0][0]);

    // ldmatrix per-lane word offsets
    const int a_row = (lane & 7) + ((lane >> 3) & 1) * 8;
    const int a_kw  = (lane >> 4) * 4;
    const int aw_off = a_row * SW + a_kw;
    const int b_row = (lane & 7) + (lane >> 4) * 8;
    const int b_kw  = ((lane >> 3) & 1) * 4;
    const int bw_off = b_row * SW + b_kw;

    uint4  aRegV[2];
    float4 aRegF[4];
    uint4  bRegV[2];

    float acc[MT][NT][4];
#pragma unroll
    for (int i = 0; i < MT; i++)
#pragma unroll
        for (int j = 0; j < NT; j++)
#pragma unroll
            for (int q = 0; q < 4; q++) acc[i][j][q] = 0.0f;

#define LOAD_A(K0)                                                            \
    if (ABF16) {                                                              \
        const __nv_bfloat16* Ab = (const __nv_bfloat16*)Av;                   \
        _Pragma("unroll")                                                     \
        for (int i = 0; i < 2; i++) {                                         \
            int fid = t + i * 256;                                            \
            int r = fid >> 2, c = fid & 3;                                    \
            int row = m0 + r;                                                 \
            aRegV[i] = make_uint4(0u, 0u, 0u, 0u);                            \
            if (row < M)                                                      \
                aRegV[i] = *(const uint4*)&Ab[(size_t)row * K + (K0) + c * 8];\
        }                                                                     \
    } else {                                                                  \
        const float* Af = (const float*)Av;                                   \
        _Pragma("unroll")                                                     \
        for (int i = 0; i < 4; i++) {                                         \
            int fid = t + i * 256;                                            \
            int r = fid >> 3, c = fid & 7;                                    \
            int row = m0 + r;                                                 \
            float4 v = make_float4(0.f, 0.f, 0.f, 0.f);                       \
            if (row < M) v = *(const float4*)&Af[(size_t)row*K + (K0) + c*4]; \
            aRegF[i] = v;                                                     \
        }                                                                     \
    }

#define STORE_A(BUF)                                                          \
    if (ABF16) {                                                              \
        _Pragma("unroll")                                                     \
        for (int i = 0; i < 2; i++) {                                         \
            int fid = t + i * 256;                                            \
            int r = fid >> 2, c = fid & 3;                                    \
            *(uint4*)&sA[BUF][r * SW + c * 4] = aRegV[i];                     \
        }                                                                     \
    } else {                                                                  \
        _Pragma("unroll")                                                     \
        for (int i = 0; i < 4; i++) {                                         \
            int fid = t + i * 256;                                            \
            int r = fid >> 3, c = fid & 7;                                    \
            float4 v = aRegF[i];                                              \
            uint2 u = make_uint2(f2bf2(v.x, v.y), f2bf2(v.z, v.w));           \
            *(uint2*)&sA[BUF][r * SW + c * 2] = u;                            \
        }                                                                     \
    }

#define LOAD_B(K0)                                                            \
    if (BN == 128) {                                                          \
        _Pragma("unroll")                                                     \
        for (int i = 0; i < 2; i++) {                                         \
            int fid = t + i * 256;                                            \
            int n = fid >> 2, c = fid & 3;                                    \
            bRegV[i] = *(const uint4*)&B[(size_t)n * K + (K0) + c * 8];       \
        }                                                                     \
    } else {                                                                  \
        int n = t >> 2, c = t & 3;                                            \
        bRegV[0] = *(const uint4*)&B[(size_t)n * K + (K0) + c * 8];           \
    }

#define STORE_B(BUF)                                                          \
    if (BN == 128) {                                                          \
        _Pragma("unroll")                                                     \
        for (int i = 0; i < 2; i++) {                                         \
            int fid = t + i * 256;                                            \
            int n = fid >> 2, c = fid & 3;                                    \
            *(uint4*)&sB[BUF][n * SW + c * 4] = bRegV[i];                     \
        }                                                                     \
    } else {                                                                  \
        int n = t >> 2, c = t & 3;                                            \
        *(uint4*)&sB[BUF][n * SW + c * 4] = bRegV[0];                         \
    }

    const int nk = K / BK;
    LOAD_A(0); LOAD_B(0);
    STORE_A(0); STORE_B(0);
    __syncthreads();

    for (int it = 0; it < nk; it++) {
        const int buf = it & 1;
        if (it + 1 < nk) { LOAD_A((it + 1) * BK); LOAD_B((it + 1) * BK); }

        const unsigned aBufU = sA_u + (unsigned)(buf * BM * SW) * 4u;
        const unsigned bBufU = sB_u + (unsigned)(buf * BN * SW) * 4u;

#pragma unroll
        for (int s = 0; s < 2; s++) {          // two k16 steps per BK=32 tile
            unsigned af[MT][4];
#pragma unroll
            for (int mt = 0; mt < MT; mt++)
                ldsm_x4(af[mt], aBufU +
                        (unsigned)((wm + mt * 16) * SW + s * 8 + aw_off) * 4u);
            unsigned bf[2][4];
#pragma unroll
            for (int p = 0; p < 2; p++)
                ldsm_x4(bf[p], bBufU +
                        (unsigned)((wn + p * 16) * SW + s * 8 + bw_off) * 4u);
#pragma unroll
            for (int mt = 0; mt < MT; mt++)
#pragma unroll
                for (int nt = 0; nt < NT; nt++)
                    mma_bf16(acc[mt][nt], af[mt], &bf[nt >> 1][(nt & 1) * 2]);
        }

        if (it + 1 < nk) {
            STORE_A(buf ^ 1); STORE_B(buf ^ 1);
            __syncthreads();
        }
    }

    // ---- epilogue ----
    if (MODE == MODE_NORM) {
        if (t < BM) sNorm[t] = 0.0f;
        __syncthreads();
#pragma unroll
        for (int mt = 0; mt < MT; mt++)
#pragma unroll
            for (int nt = 0; nt < NT; nt++) {
                int col = wn + nt * 8 + 2 * tidg;
#pragma unroll
                for (int half = 0; half < 2; half++) {
                    int rl = wm + mt * 16 + gid + half * 8;
                    if (m0 + rl >= M) continue;
                    float v0 = acc[mt][nt][half * 2 + 0] + bias[col];
                    float v1 = acc[mt][nt][half * 2 + 1] + bias[col + 1];
                    acc[mt][nt][half * 2 + 0] = v0;
                    acc[mt][nt][half * 2 + 1] = v1;
                    atomicAdd(&sNorm[rl], v0 * v0 + v1 * v1);
                }
            }
        __syncthreads();
        if (t < BM) sNorm[t] = 1.0f / fmaxf(sqrtf(sNorm[t]), 1e-12f);
        __syncthreads();
    }

#pragma unroll
    for (int mt = 0; mt < MT; mt++)
#pragma unroll
        for (int nt = 0; nt < NT; nt++) {
            int col = wn + nt * 8 + 2 * tidg;
#pragma unroll
            for (int half = 0; half < 2; half++) {
                int rl = wm + mt * 16 + gid + half * 8;
                int row = m0 + rl;
                if (row >= M) continue;
                float v0 = acc[mt][nt][half * 2 + 0];
                float v1 = acc[mt][nt][half * 2 + 1];
                if (MODE == MODE_NORM) {
                    float inv = sNorm[rl];
                    v0 *= inv; v1 *= inv;
                } else if (MODE == MODE_LIN) {
                    v0 = leaky_(v0 + bias[col]) + aux[(size_t)row * BN + col];
                    v1 = leaky_(v1 + bias[col + 1]) + aux[(size_t)row * BN + col + 1];
                } else if (MODE == MODE_G) {
                    v0 = leaky_(v0 + bias[col] + aux[(size_t)row * BN + col]);
                    v1 = leaky_(v1 + bias[col + 1] + aux[(size_t)row * BN + col + 1]);
                }
                if (OUTBF16) {
                    __nv_bfloat16* C = (__nv_bfloat16*)Cv;
                    *(__nv_bfloat162*)&C[(size_t)row * BN + col] =
                        __floats2bfloat162_rn(v0, v1);
                } else {
                    float* C = (float*)Cv;
                    *(float2*)&C[(size_t)row * BN + col] = make_float2(v0, v1);
                }
            }
        }
#undef LOAD_A
#undef STORE_A
#undef LOAD_B
#undef STORE_B
}

// ---------------------------------------------------------------------------
// Weight transpose + bf16 convert: src [Kdim][Ndim] fp32 -> dst [Ndim][Kdim] bf16
// ---------------------------------------------------------------------------
__global__ void transpose_cvt(const float* __restrict__ src,
                              __nv_bfloat16* __restrict__ dst, int Kdim, int Ndim)
{
    int i = blockIdx.x * 256 + threadIdx.x;
    if (i < Kdim * Ndim) {
        int k = i / Ndim, n = i % Ndim;
        dst[(size_t)n * Kdim + k] = __float2bfloat16(src[i]);
    }
}

// Plain elementwise fp32 -> bf16 (4 per thread)
__global__ void cvt_bf16(const float* __restrict__ src,
                         __nv_bfloat16* __restrict__ dst, int n)
{
    int i = (blockIdx.x * 256 + threadIdx.x) * 4;
    if (i < n) {
        float4 v = *(const float4*)&src[i];
        uint2 u = make_uint2(f2bf2(v.x, v.y), f2bf2(v.z, v.w));
        *(uint2*)&dst[i] = u;
    }
}

// ---------------------------------------------------------------------------
// Fused copy + row-wise L2 normalize for preference rows; bf16 output
// ---------------------------------------------------------------------------
__global__ void pref_norm_kernel(const float* __restrict__ src,
                                 __nv_bfloat16* __restrict__ dst, int nrows)
{
    int warp = (blockIdx.x * blockDim.x + threadIdx.x) >> 5;
    int lane = threadIdx.x & 31;
    if (warp >= nrows) return;
    float4 v = *(const float4*)&src[(size_t)warp * 128 + lane * 4];
    float ss = v.x * v.x + v.y * v.y + v.z * v.z + v.w * v.w;
#pragma unroll
    for (int o = 16; o; o >>= 1) ss += __shfl_xor_sync(0xffffffffu, ss, o);
    float inv = 1.0f / fmaxf(sqrtf(ss), 1e-12f);
    uint2 u = make_uint2(f2bf2(v.x * inv, v.y * inv), f2bf2(v.z * inv, v.w * inv));
    *(uint2*)&dst[(size_t)warp * 128 + lane * 4] = u;
}

// ---------------------------------------------------------------------------
// CSR build: histogram of dst, 3-phase exclusive scan, src reorder by dst
// ---------------------------------------------------------------------------
__global__ void hist_kernel(const int* __restrict__ ei, int* __restrict__ cnt)
{
    int e = blockIdx.x * blockDim.x + threadIdx.x;
    if (e < NE_) atomicAdd(&cnt[__ldg(&ei[NE_ + e])], 1);
}

__global__ void scan1_kernel(const int* __restrict__ in, int* __restrict__ out,
                             int* __restrict__ part, int n)
{
    __shared__ int s[1024];
    int i = blockIdx.x * 1024 + threadIdx.x;
    int v = (i < n) ? in[i] : 0;
    s[threadIdx.x] = v;
    __syncthreads();
#pragma unroll
    for (int o = 1; o < 1024; o <<= 1) {
        int y = (threadIdx.x >= o) ? s[threadIdx.x - o] : 0;
        __syncthreads();
        s[threadIdx.x] += y;
        __syncthreads();
    }
    if (i < n) out[i] = s[threadIdx.x] - v;
    if (threadIdx.x == 1023) part[blockIdx.x] = s[1023];
}

__global__ void scan2_kernel(int* __restrict__ part, int nb)
{
    __shared__ int s[128];
    int v = (threadIdx.x < nb) ? part[threadIdx.x] : 0;
    s[threadIdx.x] = v;
    __syncthreads();
#pragma unroll
    for (int o = 1; o < 128; o <<= 1) {
        int y = (threadIdx.x >= o) ? s[threadIdx.x - o] : 0;
        __syncthreads();
        s[threadIdx.x] += y;
        __syncthreads();
    }
    if (threadIdx.x < nb) part[threadIdx.x] = s[threadIdx.x] - v;  // exclusive
}

__global__ void scan3_kernel(int* __restrict__ out, const int* __restrict__ part, int n)
{
    int i = blockIdx.x * 1024 + threadIdx.x;
    if (i < n) out[i] += part[blockIdx.x];
}

__global__ void reorder_kernel(const int* __restrict__ ei, int* __restrict__ pos,
                               int* __restrict__ srcs)
{
    int e = blockIdx.x * blockDim.x + threadIdx.x;
    if (e >= NE_) return;
    int d = __ldg(&ei[NE_ + e]);
    int idx = atomicAdd(&pos[d], 1);
    srcs[idx] = __ldg(&ei[e]);
}

// ---------------------------------------------------------------------------
// Atomic-free segmented scatter over bf16 xw (16B lanes); fp32 accumulate;
// output = leaky(sum) as bf16.
// ---------------------------------------------------------------------------
template <int D>
__global__ void seg_scatter(const __nv_bfloat16* __restrict__ xw,
                            const int* __restrict__ offs,
                            const int* __restrict__ srcs,
                            __nv_bfloat16* __restrict__ h)
{
    constexpr int G = D / 8;
    int gt   = blockIdx.x * blockDim.x + threadIdx.x;
    int node = gt / G;
    int q    = threadIdx.x % G;
    if (node >= NN_) return;

    int s   = __ldg(&offs[node]);
    int end = __ldg(&offs[node + 1]);

    float a[8] = {0,0,0,0,0,0,0,0};
    float b[8] = {0,0,0,0,0,0,0,0};

#define ACC8(dst, u)                                                        \
    {                                                                       \
        float2 f;                                                           \
        f = __bfloat1622float2(*(const __nv_bfloat162*)&(u).x);             \
        dst[0] += f.x; dst[1] += f.y;                                       \
        f = __bfloat1622float2(*(const __nv_bfloat162*)&(u).y);             \
        dst[2] += f.x; dst[3] += f.y;                                       \
        f = __bfloat1622float2(*(const __nv_bfloat162*)&(u).z);             \
        dst[4] += f.x; dst[5] += f.y;                                       \
        f = __bfloat1622float2(*(const __nv_bfloat162*)&(u).w);             \
        dst[6] += f.x; dst[7] += f.y;                                       \
    }

    int i = s;
    for (; i + 3 < end; i += 4) {
        int s0 = __ldg(&srcs[i + 0]);
        int s1 = __ldg(&srcs[i + 1]);
        int s2 = __ldg(&srcs[i + 2]);
        int s3 = __ldg(&srcs[i + 3]);
        uint4 u0 = *(const uint4*)&xw[(size_t)s0 * D + q * 8];
        uint4 u1 = *(const uint4*)&xw[(size_t)s1 * D + q * 8];
        uint4 u2 = *(const uint4*)&xw[(size_t)s2 * D + q * 8];
        uint4 u3 = *(const uint4*)&xw[(size_t)s3 * D + q * 8];
        ACC8(a, u0); ACC8(b, u1); ACC8(a, u2); ACC8(b, u3);
    }
    for (; i < end; i++) {
        int s0 = __ldg(&srcs[i]);
        uint4 u0 = *(const uint4*)&xw[(size_t)s0 * D + q * 8];
        ACC8(a, u0);
    }
#undef ACC8

    uint4 r;
    r.x = f2bf2(leaky_(a[0] + b[0]), leaky_(a[1] + b[1]));
    r.y = f2bf2(leaky_(a[2] + b[2]), leaky_(a[3] + b[3]));
    r.z = f2bf2(leaky_(a[4] + b[4]), leaky_(a[5] + b[5]));
    r.w = f2bf2(leaky_(a[6] + b[6]), leaky_(a[7] + b[7]));
    *(uint4*)&h[(size_t)node * D + q * 8] = r;
}

// ---------------------------------------------------------------------------
extern "C" void kernel_launch(void* const* d_in, const int* in_sizes, int n_in,
                              void* d_out, int out_size)
{
    const float* features = (const float*)d_in[0];
    const float* id_emb   = (const float*)d_in[1];
    const float* pref     = (const float*)d_in[2];
    const float* mlp_w    = (const float*)d_in[3];
    const float* mlp_b    = (const float*)d_in[4];
    const float* conv1_w  = (const float*)d_in[5];
    const float* lin1_w   = (const float*)d_in[6];
    const float* lin1_b   = (const float*)d_in[7];
    const float* g1_w     = (const float*)d_in[8];
    const float* g1_b     = (const float*)d_in[9];
    const float* conv2_w  = (const float*)d_in[10];
    const float* lin2_w   = (const float*)d_in[11];
    const float* lin2_b   = (const float*)d_in[12];
    const float* g2_w     = (const float*)d_in[13];
    const float* g2_b     = (const float*)d_in[14];
    const int*   ei       = (const int*)d_in[15];
    float* out = (float*)d_out;

    float *pxhat;
    __nv_bfloat16 *px, *pxw, *ph, *px2;
    __nv_bfloat16 *pwmlp, *pwc1, *pwc2, *pwlin1, *pwg1, *pwlin2, *pwg2;
    int *pcnt, *poffs, *ppart, *ppos, *psrcs;
    cudaGetSymbolAddress((void**)&px,     g_x);
    cudaGetSymbolAddress((void**)&pxw,    g_xw);
    cudaGetSymbolAddress((void**)&ph,     g_h);
    cudaGetSymbolAddress((void**)&px2,    g_x2);
    cudaGetSymbolAddress((void**)&pxhat,  g_xhat);
    cudaGetSymbolAddress((void**)&pwmlp,  g_wmlp);
    cudaGetSymbolAddress((void**)&pwc1,   g_wc1);
    cudaGetSymbolAddress((void**)&pwc2,   g_wc2);
    cudaGetSymbolAddress((void**)&pwlin1, g_wlin1);
    cudaGetSymbolAddress((void**)&pwg1,   g_wg1);
    cudaGetSymbolAddress((void**)&pwlin2, g_wlin2);
    cudaGetSymbolAddress((void**)&pwg2,   g_wg2);
    cudaGetSymbolAddress((void**)&pcnt,   g_cnt);
    cudaGetSymbolAddress((void**)&poffs,  g_offs);
    cudaGetSymbolAddress((void**)&ppart,  g_part);
    cudaGetSymbolAddress((void**)&ppos,   g_pos);
    cudaGetSymbolAddress((void**)&psrcs,  g_srcs);

    const int GB_N  = (NN_ + 127) / 128;
    const int NSCAN = NN_ + 1;
    const int NBLK  = (NSCAN + 1023) / 1024;

    static cudaStream_t s_side = nullptr;
    static cudaEvent_t ev_fork = nullptr, ev_join = nullptr, ev_mlp = nullptr,
                       ev_w = nullptr, ev_lin1 = nullptr, ev_g1 = nullptr,
                       ev_lin2 = nullptr;
    if (!s_side) {
        cudaStreamCreateWithFlags(&s_side, cudaStreamNonBlocking);
        cudaEventCreateWithFlags(&ev_fork, cudaEventDisableTiming);
        cudaEventCreateWithFlags(&ev_join, cudaEventDisableTiming);
        cudaEventCreateWithFlags(&ev_mlp,  cudaEventDisableTiming);
        cudaEventCreateWithFlags(&ev_w,    cudaEventDisableTiming);
        cudaEventCreateWithFlags(&ev_lin1, cudaEventDisableTiming);
        cudaEventCreateWithFlags(&ev_g1,   cudaEventDisableTiming);
        cudaEventCreateWithFlags(&ev_lin2, cudaEventDisableTiming);
    }

    // ---- fork: weight prep first (MLP waits only on mlp_w), then CSR ----
    cudaEventRecord(ev_fork, 0);
    cudaStreamWaitEvent(s_side, ev_fork, 0);
    cvt_bf16<<<(DL_ * DF_ / 4 + 255) / 256, 256, 0, s_side>>>(mlp_w, pwmlp, DL_ * DF_);
    cudaEventRecord(ev_w, s_side);
    cudaMemsetAsync(pcnt, 0, NSCAN * sizeof(int), s_side);
    hist_kernel<<<(NE_ + 255) / 256, 256, 0, s_side>>>(ei, pcnt);
    scan1_kernel<<<NBLK, 1024, 0, s_side>>>(pcnt, poffs, ppart, NSCAN);
    scan2_kernel<<<1, 128, 0, s_side>>>(ppart, NBLK);
    scan3_kernel<<<NBLK, 1024, 0, s_side>>>(poffs, ppart, NSCAN);

    // ---- main: MLP (x[NU:] = normalize(features @ mlp_w^T + mlp_b))
    cudaStreamWaitEvent(0, ev_w, 0);
    mma_gemm<128, MODE_NORM, false, true><<<(NI_ + 127) / 128, 256>>>(
        features, pwmlp, px + (size_t)NU_ * DL_, NI_, DF_, mlp_b, nullptr);
    cudaEventRecord(ev_mlp, 0);

    // ---- remaining side-stream work ----
    cudaMemcpyAsync(ppos, poffs, NN_ * sizeof(int), cudaMemcpyDeviceToDevice, s_side);
    reorder_kernel<<<(NE_ + 255) / 256, 256, 0, s_side>>>(ei, ppos, psrcs);
    transpose_cvt<<<(DL_ * DL_ + 255) / 256, 256, 0, s_side>>>(conv1_w, pwc1, DL_, DL_);
    transpose_cvt<<<(DI_ * DI_ + 255) / 256, 256, 0, s_side>>>(conv2_w, pwc2, DI_, DI_);
    cvt_bf16<<<(DI_ * DL_ / 4 + 255) / 256, 256, 0, s_side>>>(lin1_w, pwlin1, DI_ * DL_);
    cvt_bf16<<<(DI_ * DL_ / 4 + 255) / 256, 256, 0, s_side>>>(g1_w, pwg1, DI_ * DL_);
    cvt_bf16<<<(DI_ * DI_ / 4 + 255) / 256, 256, 0, s_side>>>(lin2_w, pwlin2, DI_ * DI_);
    cvt_bf16<<<(DI_ * DI_ / 4 + 255) / 256, 256, 0, s_side>>>(g2_w, pwg2, DI_ * DI_);
    pref_norm_kernel<<<(NU_ * 32 + 255) / 256, 256, 0, s_side>>>(pref, px, NU_);
    cudaEventRecord(ev_join, s_side);

    // side: lin1 overlapped with conv1+scatter (waits MLP)
    cudaStreamWaitEvent(s_side, ev_mlp, 0);
    mma_gemm<64, MODE_LIN, true, false><<<GB_N, 256, 0, s_side>>>(
        px, pwlin1, pxhat, NN_, DL_, lin1_b, id_emb);
    cudaEventRecord(ev_lin1, s_side);

    cudaStreamWaitEvent(0, ev_join, 0);

    // ===== layer 1 (main) =====
    mma_gemm<128, MODE_PLAIN, true, true><<<GB_N, 256>>>(
        px, pwc1, pxw, NN_, DL_, nullptr, nullptr);
    seg_scatter<128><<<(NN_ * 16 + 255) / 256, 256>>>(pxw, poffs, psrcs, ph);
    cudaStreamWaitEvent(0, ev_lin1, 0);
    mma_gemm<64, MODE_G, true, true><<<GB_N, 256>>>(
        ph, pwg1, px2, NN_, DL_, g1_b, pxhat);
    cudaEventRecord(ev_g1, 0);

    // side: lin2 overlapped with conv2+scatter64
    cudaStreamWaitEvent(s_side, ev_g1, 0);
    mma_gemm<64, MODE_LIN, true, false><<<GB_N, 256, 0, s_side>>>(
        px2, pwlin2, pxhat, NN_, DI_, lin2_b, id_emb);
    cudaEventRecord(ev_lin2, s_side);

    // ===== layer 2 (main) =====
    mma_gemm<64, MODE_PLAIN, true, true><<<GB_N, 256>>>(
        px2, pwc2, pxw, NN_, DI_, nullptr, nullptr);
    seg_scatter<64><<<(NN_ * 8 + 255) / 256, 256>>>(pxw, poffs, psrcs, ph);
    cudaStreamWaitEvent(0, ev_lin2, 0);
    mma_gemm<64, MODE_G, true, false><<<GB_N, 256>>>(
        ph, pwg2, out, NN_, DI_, g2_b, pxhat);
}